// round 10
// baseline (speedup 1.0000x reference)
#include <cuda_runtime.h>
#include <math.h>

#define D_MODEL  1024
#define N_HEADS  16
#define HEAD_DIM 64
#define BATCH    4
#define SEQ      2048
#define M_TOK    (BATCH * SEQ)   // 8192

// Scratch (allocation-free rule: __device__ globals)
__device__ float g_qkv[(size_t)M_TOK * 3 * D_MODEL];  // 96 MB
__device__ float g_att[(size_t)M_TOK * D_MODEL];      // 32 MB

// ---------------------------------------------------------------------------
// SGEMM: C[M,N] = A[M,K] @ W[N,K]^T (verified == naive in R3)
// ---------------------------------------------------------------------------
__global__ __launch_bounds__(256) void sgemm_nt_128x128(
    const float* __restrict__ A, const float* __restrict__ W,
    float* __restrict__ C, int M, int N, int K)
{
    __shared__ float As[32][132];
    __shared__ float Bs[32][132];

    const int tid = threadIdx.x;
    const int tx  = tid & 15;
    const int ty  = tid >> 4;
    const size_t arow0 = (size_t)blockIdx.y * 128;
    const size_t brow0 = (size_t)blockIdx.x * 128;
    const float* Ab = A + arow0 * (size_t)K;
    const float* Wb = W + brow0 * (size_t)K;

    float acc[8][8];
    #pragma unroll
    for (int i = 0; i < 8; i++)
        #pragma unroll
        for (int j = 0; j < 8; j++) acc[i][j] = 0.f;

    for (int k0 = 0; k0 < K; k0 += 32) {
        #pragma unroll
        for (int i = 0; i < 4; i++) {
            int idx = tid + i * 256;
            int row = idx >> 3;
            int c4  = (idx & 7) * 4;
            float4 va = *(const float4*)(Ab + (size_t)row * K + k0 + c4);
            As[c4 + 0][row] = va.x; As[c4 + 1][row] = va.y;
            As[c4 + 2][row] = va.z; As[c4 + 3][row] = va.w;
            float4 vb = *(const float4*)(Wb + (size_t)row * K + k0 + c4);
            Bs[c4 + 0][row] = vb.x; Bs[c4 + 1][row] = vb.y;
            Bs[c4 + 2][row] = vb.z; Bs[c4 + 3][row] = vb.w;
        }
        __syncthreads();
        #pragma unroll
        for (int kk = 0; kk < 32; kk++) {
            float a[8], b[8];
            *(float4*)&a[0] = *(const float4*)&As[kk][ty * 8];
            *(float4*)&a[4] = *(const float4*)&As[kk][ty * 8 + 4];
            *(float4*)&b[0] = *(const float4*)&Bs[kk][tx * 8];
            *(float4*)&b[4] = *(const float4*)&Bs[kk][tx * 8 + 4];
            #pragma unroll
            for (int i = 0; i < 8; i++)
                #pragma unroll
                for (int j = 0; j < 8; j++)
                    acc[i][j] += a[i] * b[j];
        }
        __syncthreads();
    }

    float* Cb = C + (arow0 + ty * 8) * (size_t)N + brow0 + tx * 8;
    #pragma unroll
    for (int i = 0; i < 8; i++) {
        float4 v0 = make_float4(acc[i][0], acc[i][1], acc[i][2], acc[i][3]);
        float4 v1 = make_float4(acc[i][4], acc[i][5], acc[i][6], acc[i][7]);
        *(float4*)(Cb + (size_t)i * N)     = v0;
        *(float4*)(Cb + (size_t)i * N + 4) = v1;
    }
}

// ---------------------------------------------------------------------------
// RoPE in-place, sign-flipped NeoX (decoded R6, verified R7).
// ---------------------------------------------------------------------------
__global__ __launch_bounds__(256) void rope_kernel()
{
    int idx = blockIdx.x * blockDim.x + threadIdx.x;
    int i   = idx & 31;
    int h   = (idx >> 5) & 15;
    int qk  = (idx >> 9) & 1;
    int tok = idx >> 10;
    int t   = tok & (SEQ - 1);

    double th = pow(10000.0, -(double)i / 32.0);
    float  f  = (float)t * (float)th;
    double cd, sd;
    sincos((double)f, &cd, &sd);
    float c = (float)cd, s = (float)sd;

    float* base = g_qkv + (size_t)tok * 3072 + qk * 1024 + h * 64 + i;
    float x1 = base[0];
    float x2 = base[32];
    base[0]  = x1 * c + x2 * s;
    base[32] = x2 * c - x1 * s;
}

// ---------------------------------------------------------------------------
// Flash attention v4 — BQ=128, BK=64, 8x4 per-thread tile, dynamic smem 96KB.
// Grid: (SEQ/128, BATCH*N_HEADS), 256 threads (tx=tid&15 -> 4 cols,
// ty=tid>>4 -> 8 rows). Layout (words):
//   QS [d=64][r=128]  swizzled rg^(d&31), reads broadcast (keyed by ty only)
//   KT [d=64][c=64]   swizzled cg^(d&15)
//   VS [k=64][d=64]   straight
//   PS [r=128][k=64]  swizzled kg^(r&15)
// ---------------------------------------------------------------------------
extern __shared__ float smem_v4[];
__global__ __launch_bounds__(256, 2) void attn_v4()
{
    float* QS = smem_v4;            // 8192 words
    float* KT = smem_v4 + 8192;     // 4096
    float* VS = smem_v4 + 12288;    // 4096
    float* PS = smem_v4 + 16384;    // 8192

    const int tid = threadIdx.x;
    const int tx  = tid & 15;
    const int ty  = tid >> 4;
    const int bx  = gridDim.x - 1 - blockIdx.x;   // heavy CTAs first
    const int bh  = blockIdx.y;
    const int b   = bh >> 4;
    const int h   = bh & 15;
    const int q0  = bx * 128;
    const size_t base = (size_t)b * SEQ * 3072;

    // Stage Q^T: 128 rows x 64 dims = 2048 float4, 8 per thread
    #pragma unroll
    for (int i = 0; i < 8; i++) {
        int idx = tid + i * 256;
        int r   = idx >> 4;
        int d4  = (idx & 15) * 4;
        float4 v = *(const float4*)(g_qkv + base + (size_t)(q0 + r) * 3072 + h * 64 + d4);
        int rg = r >> 2, rw = r & 3;
        QS[(d4 + 0) * 128 + ((rg ^ ((d4 + 0) & 31)) << 2) + rw] = v.x;
        QS[(d4 + 1) * 128 + ((rg ^ ((d4 + 1) & 31)) << 2) + rw] = v.y;
        QS[(d4 + 2) * 128 + ((rg ^ ((d4 + 2) & 31)) << 2) + rw] = v.z;
        QS[(d4 + 3) * 128 + ((rg ^ ((d4 + 3) & 31)) << 2) + rw] = v.w;
    }

    float o[8][4];
    float m[8], l[8];
    #pragma unroll
    for (int i = 0; i < 8; i++) {
        m[i] = -1e30f; l[i] = 0.f;
        #pragma unroll
        for (int j = 0; j < 4; j++) o[i][j] = 0.f;
    }

    const int nch = 2 * (bx + 1);

    for (int kb = 0; kb < nch; kb++) {
        const int j0 = kb * 64;
        __syncthreads();   // prev chunk done with KT/VS/PS; Q staged (first)

        // Stage K^T (swizzled) and V (straight): 64x64 each, 4 float4/thread
        #pragma unroll
        for (int i = 0; i < 4; i++) {
            int idx = tid + i * 256;
            int c   = idx >> 4;
            int d4  = (idx & 15) * 4;
            const float* kp = g_qkv + base + (size_t)(j0 + c) * 3072 + 1024 + h * 64 + d4;
            float4 kv = *(const float4*)kp;
            float4 vv = *(const float4*)(kp + 1024);
            *(float4*)&VS[c * 64 + d4] = vv;
            int cg = c >> 2, cw = c & 3;
            KT[(d4 + 0) * 64 + ((cg ^ ((d4 + 0) & 15)) << 2) + cw] = kv.x;
            KT[(d4 + 1) * 64 + ((cg ^ ((d4 + 1) & 15)) << 2) + cw] = kv.y;
            KT[(d4 + 2) * 64 + ((cg ^ ((d4 + 2) & 15)) << 2) + cw] = kv.z;
            KT[(d4 + 3) * 64 + ((cg ^ ((d4 + 3) & 15)) << 2) + cw] = kv.w;
        }
        __syncthreads();

        // S = Q K^T : 8x4 register tile
        float s[8][4];
        #pragma unroll
        for (int i = 0; i < 8; i++)
            #pragma unroll
            for (int j = 0; j < 4; j++) s[i][j] = 0.f;

        #pragma unroll 8
        for (int d = 0; d < 64; d++) {
            float4 alo = *(const float4*)&QS[d * 128 + (((ty * 2)     ^ (d & 31)) << 2)];
            float4 ahi = *(const float4*)&QS[d * 128 + (((ty * 2 + 1) ^ (d & 31)) << 2)];
            float4 k   = *(const float4*)&KT[d * 64  + ((tx ^ (d & 15)) << 2)];
            s[0][0] += alo.x * k.x; s[0][1] += alo.x * k.y; s[0][2] += alo.x * k.z; s[0][3] += alo.x * k.w;
            s[1][0] += alo.y * k.x; s[1][1] += alo.y * k.y; s[1][2] += alo.y * k.z; s[1][3] += alo.y * k.w;
            s[2][0] += alo.z * k.x; s[2][1] += alo.z * k.y; s[2][2] += alo.z * k.z; s[2][3] += alo.z * k.w;
            s[3][0] += alo.w * k.x; s[3][1] += alo.w * k.y; s[3][2] += alo.w * k.z; s[3][3] += alo.w * k.w;
            s[4][0] += ahi.x * k.x; s[4][1] += ahi.x * k.y; s[4][2] += ahi.x * k.z; s[4][3] += ahi.x * k.w;
            s[5][0] += ahi.y * k.x; s[5][1] += ahi.y * k.y; s[5][2] += ahi.y * k.z; s[5][3] += ahi.y * k.w;
            s[6][0] += ahi.z * k.x; s[6][1] += ahi.z * k.y; s[6][2] += ahi.z * k.z; s[6][3] += ahi.z * k.w;
            s[7][0] += ahi.w * k.x; s[7][1] += ahi.w * k.y; s[7][2] += ahi.w * k.z; s[7][3] += ahi.w * k.w;
        }

        // scale + causal mask (last two chunks of this q-tile need masking)
        if (kb >= 2 * bx) {
            #pragma unroll
            for (int i = 0; i < 8; i++) {
                int qrow = q0 + ty * 8 + i;
                #pragma unroll
                for (int j = 0; j < 4; j++)
                    s[i][j] = (j0 + tx * 4 + j <= qrow) ? s[i][j] * 0.125f : -1e30f;
            }
        } else {
            #pragma unroll
            for (int i = 0; i < 8; i++)
                #pragma unroll
                for (int j = 0; j < 4; j++) s[i][j] *= 0.125f;
        }

        // online softmax: reduce across 16 tx-lanes (lane = (ty&1)*16 + tx)
        #pragma unroll
        for (int i = 0; i < 8; i++) {
            float rm = fmaxf(fmaxf(s[i][0], s[i][1]), fmaxf(s[i][2], s[i][3]));
            #pragma unroll
            for (int off = 8; off > 0; off >>= 1)
                rm = fmaxf(rm, __shfl_xor_sync(0xffffffffu, rm, off));
            float m_new = fmaxf(m[i], rm);
            float alpha = __expf(m[i] - m_new);
            m[i] = m_new;
            #pragma unroll
            for (int j = 0; j < 4; j++) s[i][j] = __expf(s[i][j] - m_new);
            float rl = s[i][0] + s[i][1] + s[i][2] + s[i][3];
            #pragma unroll
            for (int off = 8; off > 0; off >>= 1)
                rl += __shfl_xor_sync(0xffffffffu, rl, off);
            l[i] = l[i] * alpha + rl;
            #pragma unroll
            for (int j = 0; j < 4; j++) o[i][j] *= alpha;
        }

        // store P swizzled (conflict-free float4 per row)
        #pragma unroll
        for (int i = 0; i < 8; i++) {
            int r = ty * 8 + i;
            *(float4*)&PS[r * 64 + ((tx ^ (r & 15)) << 2)] =
                make_float4(s[i][0], s[i][1], s[i][2], s[i][3]);
        }
        __syncthreads();

        // O += P V  (p reads broadcast; V reads conflict-free)
        #pragma unroll 4
        for (int k4 = 0; k4 < 16; k4++) {
            float4 p[8];
            #pragma unroll
            for (int i = 0; i < 8; i++) {
                int r = ty * 8 + i;
                p[i] = *(const float4*)&PS[r * 64 + ((k4 ^ (r & 15)) << 2)];
            }
            #pragma unroll
            for (int kk = 0; kk < 4; kk++) {
                float4 v = *(const float4*)&VS[(k4 * 4 + kk) * 64 + tx * 4];
                #pragma unroll
                for (int i = 0; i < 8; i++) {
                    float pi = ((const float*)&p[i])[kk];
                    o[i][0] += pi * v.x; o[i][1] += pi * v.y;
                    o[i][2] += pi * v.z; o[i][3] += pi * v.w;
                }
            }
        }
    }

    // epilogue: normalize and store
    #pragma unroll
    for (int i = 0; i < 8; i++) {
        float inv = 1.0f / l[i];
        float4 w = make_float4(o[i][0] * inv, o[i][1] * inv,
                               o[i][2] * inv, o[i][3] * inv);
        *(float4*)(g_att + ((size_t)b * SEQ + q0 + ty * 8 + i) * 1024
                   + h * 64 + tx * 4) = w;
    }
}

// ---------------------------------------------------------------------------
extern "C" void kernel_launch(void* const* d_in, const int* in_sizes, int n_in,
                              void* d_out, int out_size)
{
    const float* x     = (const float*)d_in[0];
    const float* w_qkv = (const float*)d_in[1];
    const float* w_out = (const float*)d_in[2];
    for (int i = 0; i < n_in; i++) {
        if      (in_sizes[i] == M_TOK * D_MODEL)       x     = (const float*)d_in[i];
        else if (in_sizes[i] == 3 * D_MODEL * D_MODEL) w_qkv = (const float*)d_in[i];
        else if (in_sizes[i] == D_MODEL * D_MODEL)     w_out = (const float*)d_in[i];
    }
    float* out = (float*)d_out;

    float *qkv = nullptr, *att = nullptr;
    cudaGetSymbolAddress((void**)&qkv, g_qkv);
    cudaGetSymbolAddress((void**)&att, g_att);

    // 1) QKV projection
    sgemm_nt_128x128<<<dim3(3 * D_MODEL / 128, M_TOK / 128), 256>>>(
        x, w_qkv, qkv, M_TOK, 3 * D_MODEL, D_MODEL);

    // 2) Sign-flipped NeoX RoPE
    rope_kernel<<<(M_TOK * 2 * N_HEADS * 32) / 256, 256>>>();

    // 3) Causal flash attention v4 (BQ=128, 96KB dynamic smem)
    const int smem_bytes = 96 * 1024;
    cudaFuncSetAttribute(attn_v4, cudaFuncAttributeMaxDynamicSharedMemorySize,
                         smem_bytes);
    attn_v4<<<dim3(SEQ / 128, BATCH * N_HEADS), 256, smem_bytes>>>();

    // 4) Output projection
    sgemm_nt_128x128<<<dim3(D_MODEL / 128, M_TOK / 128), 256>>>(
        att, w_out, out, M_TOK, D_MODEL, D_MODEL);
}

// round 11
// speedup vs baseline: 1.0165x; 1.0165x over previous
#include <cuda_runtime.h>
#include <math.h>
#include <stdint.h>

#define D_MODEL  1024
#define N_HEADS  16
#define HEAD_DIM 64
#define BATCH    4
#define SEQ      2048
#define M_TOK    (BATCH * SEQ)   // 8192

// Scratch (allocation-free rule: __device__ globals)
__device__ float g_qkv[(size_t)M_TOK * 3 * D_MODEL];  // 96 MB
__device__ float g_att[(size_t)M_TOK * D_MODEL];      // 32 MB

// ---------------------------------------------------------------------------
// TF32 tensor-core GEMM with hi/lo split (fp32-class accuracy).
// C[M,N] = A[M,K] @ W[N,K]^T.  CTA tile 128x128, BK=32, 256 threads.
// Warp grid 2(M)x4(N); warp tile 64x32 = 4x4 m16n8k8 fragments.
// Smem holds tf32 fragments in [lane][reg] order (conflict-free LDS.128/64).
// 3 passes: aH*bH + aL*bH + aH*bL  (lo*lo negligible).
// ---------------------------------------------------------------------------
#define MMA_TF32(d, a, b)                                                    \
    asm volatile(                                                            \
        "mma.sync.aligned.m16n8k8.row.col.f32.tf32.tf32.f32 "                \
        "{%0,%1,%2,%3}, {%4,%5,%6,%7}, {%8,%9}, {%0,%1,%2,%3};"              \
        : "+f"(d[0]), "+f"(d[1]), "+f"(d[2]), "+f"(d[3])                     \
        : "r"(a[0]), "r"(a[1]), "r"(a[2]), "r"(a[3]), "r"(b[0]), "r"(b[1]))

__device__ __forceinline__ void cvt_hilo(float f, uint32_t& hi, uint32_t& lo)
{
    asm("cvt.rna.tf32.f32 %0, %1;" : "=r"(hi) : "f"(f));
    float r = f - __uint_as_float(hi);
    asm("cvt.rna.tf32.f32 %0, %1;" : "=r"(lo) : "f"(r));
}

extern __shared__ uint32_t gsm[];
__global__ __launch_bounds__(256) void gemm_tf32_128x128(
    const float* __restrict__ A, const float* __restrict__ W,
    float* __restrict__ C, int M, int N, int K)
{
    uint32_t* AsH = gsm;            // [mtile8][kstep4][lane32][reg4] = 4096
    uint32_t* AsL = gsm + 4096;
    uint32_t* BsH = gsm + 8192;     // [ntile16][kstep4][lane32][reg2] = 4096
    uint32_t* BsL = gsm + 12288;    // total 64 KB

    const int tid  = threadIdx.x;
    const int wid  = tid >> 5;
    const int lane = tid & 31;
    const int wm   = wid & 1;       // 2 warps over M
    const int wn   = wid >> 1;      // 4 warps over N
    const size_t arow0 = (size_t)blockIdx.y * 128;
    const size_t brow0 = (size_t)blockIdx.x * 128;

    float acc[4][4][4];
    #pragma unroll
    for (int mt = 0; mt < 4; mt++)
        #pragma unroll
        for (int nt = 0; nt < 4; nt++)
            #pragma unroll
            for (int r = 0; r < 4; r++) acc[mt][nt][r] = 0.f;

    for (int k0 = 0; k0 < K; k0 += 32) {
        __syncthreads();   // previous chunk fully consumed

        // --- stage A (128x32) into fragment layout, tf32 hi/lo ---
        #pragma unroll
        for (int i = 0; i < 4; i++) {
            int idx = tid + i * 256;
            int row = idx >> 3;
            int c4  = (idx & 7) * 4;
            float4 v = *(const float4*)(A + (arow0 + row) * (size_t)K + k0 + c4);
            int mt = row >> 4, ri = row & 15;
            int ks = c4 >> 3;
            int rb = ((ri >> 3) & 1) + (((c4 & 7) >= 4) ? 2 : 0);
            int lb = (ri & 7) * 4;
            float vv[4] = {v.x, v.y, v.z, v.w};
            #pragma unroll
            for (int j = 0; j < 4; j++) {
                uint32_t hi, lo;
                cvt_hilo(vv[j], hi, lo);
                int off = ((mt * 4 + ks) * 32 + lb + j) * 4 + rb;
                AsH[off] = hi; AsL[off] = lo;
            }
        }
        // --- stage B = W (128x32) ---
        #pragma unroll
        for (int i = 0; i < 4; i++) {
            int idx = tid + i * 256;
            int n   = idx >> 3;
            int k4  = (idx & 7) * 4;
            float4 v = *(const float4*)(W + (brow0 + n) * (size_t)K + k0 + k4);
            int nt = n >> 3, nin = n & 7;
            int ks = k4 >> 3;
            int rg = ((k4 & 7) >= 4) ? 1 : 0;
            float vv[4] = {v.x, v.y, v.z, v.w};
            #pragma unroll
            for (int j = 0; j < 4; j++) {
                uint32_t hi, lo;
                cvt_hilo(vv[j], hi, lo);
                int off = ((nt * 4 + ks) * 32 + nin * 4 + j) * 2 + rg;
                BsH[off] = hi; BsL[off] = lo;
            }
        }
        __syncthreads();

        // --- compute: 4 k-steps x 4 mtiles x 4 ntiles x 3 passes ---
        #pragma unroll
        for (int ks = 0; ks < 4; ks++) {
            uint32_t bh[4][2], bl[4][2];
            #pragma unroll
            for (int nt = 0; nt < 4; nt++) {
                int off = (((wn * 4 + nt) * 4 + ks) * 32 + lane) * 2;
                uint2 h = *(const uint2*)&BsH[off];
                uint2 l = *(const uint2*)&BsL[off];
                bh[nt][0] = h.x; bh[nt][1] = h.y;
                bl[nt][0] = l.x; bl[nt][1] = l.y;
            }
            #pragma unroll
            for (int mt = 0; mt < 4; mt++) {
                int off = (((wm * 4 + mt) * 4 + ks) * 32 + lane) * 4;
                uint4 h = *(const uint4*)&AsH[off];
                uint4 l = *(const uint4*)&AsL[off];
                uint32_t ah[4] = {h.x, h.y, h.z, h.w};
                uint32_t al[4] = {l.x, l.y, l.z, l.w};
                #pragma unroll
                for (int nt = 0; nt < 4; nt++) {
                    MMA_TF32(acc[mt][nt], ah, bh[nt]);
                    MMA_TF32(acc[mt][nt], al, bh[nt]);
                    MMA_TF32(acc[mt][nt], ah, bl[nt]);
                }
            }
        }
    }

    // --- epilogue: fragment -> global ---
    #pragma unroll
    for (int mt = 0; mt < 4; mt++) {
        size_t row = arow0 + wm * 64 + mt * 16 + (lane >> 2);
        #pragma unroll
        for (int nt = 0; nt < 4; nt++) {
            size_t col = brow0 + wn * 32 + nt * 8 + (lane & 3) * 2;
            *(float2*)(C + row * N + col) =
                make_float2(acc[mt][nt][0], acc[mt][nt][1]);
            *(float2*)(C + (row + 8) * N + col) =
                make_float2(acc[mt][nt][2], acc[mt][nt][3]);
        }
    }
}

// ---------------------------------------------------------------------------
// RoPE in-place, sign-flipped NeoX (decoded R6, verified R7).
// ---------------------------------------------------------------------------
__global__ __launch_bounds__(256) void rope_kernel()
{
    int idx = blockIdx.x * blockDim.x + threadIdx.x;
    int i   = idx & 31;
    int h   = (idx >> 5) & 15;
    int qk  = (idx >> 9) & 1;
    int tok = idx >> 10;
    int t   = tok & (SEQ - 1);

    double th = pow(10000.0, -(double)i / 32.0);
    float  f  = (float)t * (float)th;
    double cd, sd;
    sincos((double)f, &cd, &sd);
    float c = (float)cd, s = (float)sd;

    float* base = g_qkv + (size_t)tok * 3072 + qk * 1024 + h * 64 + i;
    float x1 = base[0];
    float x2 = base[32];
    base[0]  = x1 * c + x2 * s;
    base[32] = x2 * c - x1 * s;
}

// ---------------------------------------------------------------------------
// Flash attention v3 (R9 winner) — XOR-swizzled smem, conflict-free hot loops.
// ---------------------------------------------------------------------------
__global__ __launch_bounds__(256) void attn_v3()
{
    __shared__ float Qs[64 * 64];
    __shared__ float KT[64 * 64];
    __shared__ float Vs[64 * 64];

    const int tid = threadIdx.x;
    const int tx  = tid & 15;
    const int ty  = tid >> 4;
    const int bx  = gridDim.x - 1 - blockIdx.x;   // heavy CTAs first
    const int bh  = blockIdx.y;
    const int b   = bh >> 4;
    const int h   = bh & 15;
    const int q0  = bx * 64;
    const size_t base = (size_t)b * SEQ * 3072;

    #pragma unroll
    for (int i = 0; i < 4; i++) {
        int idx = tid + i * 256;
        int r   = idx >> 4;
        int d4  = (idx & 15) * 4;
        float4 v = *(const float4*)(g_qkv + base + (size_t)(q0 + r) * 3072 + h * 64 + d4);
        int rg = r >> 2, rw = r & 3;
        Qs[(d4 + 0) * 64 + ((rg ^ ((d4 + 0) & 15)) << 2) + rw] = v.x;
        Qs[(d4 + 1) * 64 + ((rg ^ ((d4 + 1) & 15)) << 2) + rw] = v.y;
        Qs[(d4 + 2) * 64 + ((rg ^ ((d4 + 2) & 15)) << 2) + rw] = v.z;
        Qs[(d4 + 3) * 64 + ((rg ^ ((d4 + 3) & 15)) << 2) + rw] = v.w;
    }

    float o[4][4];
    float m[4], l[4];
    #pragma unroll
    for (int i = 0; i < 4; i++) {
        m[i] = -1e30f; l[i] = 0.f;
        #pragma unroll
        for (int j = 0; j < 4; j++) o[i][j] = 0.f;
    }

    for (int kb = 0; kb <= bx; kb++) {
        const int j0 = kb * 64;
        __syncthreads();

        #pragma unroll
        for (int i = 0; i < 4; i++) {
            int idx = tid + i * 256;
            int c   = idx >> 4;
            int d4  = (idx & 15) * 4;
            const float* kp = g_qkv + base + (size_t)(j0 + c) * 3072 + 1024 + h * 64 + d4;
            float4 kv = *(const float4*)kp;
            float4 vv = *(const float4*)(kp + 1024);
            *(float4*)&Vs[c * 64 + d4] = vv;
            int cg = c >> 2, cw = c & 3;
            KT[(d4 + 0) * 64 + ((cg ^ ((d4 + 0) & 15)) << 2) + cw] = kv.x;
            KT[(d4 + 1) * 64 + ((cg ^ ((d4 + 1) & 15)) << 2) + cw] = kv.y;
            KT[(d4 + 2) * 64 + ((cg ^ ((d4 + 2) & 15)) << 2) + cw] = kv.z;
            KT[(d4 + 3) * 64 + ((cg ^ ((d4 + 3) & 15)) << 2) + cw] = kv.w;
        }
        __syncthreads();

        float s[4][4];
        #pragma unroll
        for (int i = 0; i < 4; i++)
            #pragma unroll
            for (int j = 0; j < 4; j++) s[i][j] = 0.f;

        #pragma unroll 16
        for (int d = 0; d < 64; d++) {
            int sw = (d & 15);
            float4 a = *(const float4*)&Qs[d * 64 + ((ty ^ sw) << 2)];
            float4 k = *(const float4*)&KT[d * 64 + ((tx ^ sw) << 2)];
            s[0][0] += a.x * k.x; s[0][1] += a.x * k.y; s[0][2] += a.x * k.z; s[0][3] += a.x * k.w;
            s[1][0] += a.y * k.x; s[1][1] += a.y * k.y; s[1][2] += a.y * k.z; s[1][3] += a.y * k.w;
            s[2][0] += a.z * k.x; s[2][1] += a.z * k.y; s[2][2] += a.z * k.z; s[2][3] += a.z * k.w;
            s[3][0] += a.w * k.x; s[3][1] += a.w * k.y; s[3][2] += a.w * k.z; s[3][3] += a.w * k.w;
        }

        if (kb == bx) {
            #pragma unroll
            for (int i = 0; i < 4; i++)
                #pragma unroll
                for (int j = 0; j < 4; j++)
                    s[i][j] = (tx * 4 + j <= ty * 4 + i) ? s[i][j] * 0.125f : -1e30f;
        } else {
            #pragma unroll
            for (int i = 0; i < 4; i++)
                #pragma unroll
                for (int j = 0; j < 4; j++) s[i][j] *= 0.125f;
        }

        float alpha[4];
        #pragma unroll
        for (int i = 0; i < 4; i++) {
            float rm = fmaxf(fmaxf(s[i][0], s[i][1]), fmaxf(s[i][2], s[i][3]));
            #pragma unroll
            for (int off = 8; off > 0; off >>= 1)
                rm = fmaxf(rm, __shfl_xor_sync(0xffffffffu, rm, off));
            float m_new = fmaxf(m[i], rm);
            alpha[i] = __expf(m[i] - m_new);
            m[i] = m_new;
            #pragma unroll
            for (int j = 0; j < 4; j++) s[i][j] = __expf(s[i][j] - m_new);
            float rl = s[i][0] + s[i][1] + s[i][2] + s[i][3];
            #pragma unroll
            for (int off = 8; off > 0; off >>= 1)
                rl += __shfl_xor_sync(0xffffffffu, rl, off);
            l[i] = l[i] * alpha[i] + rl;
            #pragma unroll
            for (int j = 0; j < 4; j++) o[i][j] *= alpha[i];
        }

        __syncthreads();

        #pragma unroll
        for (int i = 0; i < 4; i++) {
            int r = ty * 4 + i;
            *(float4*)&KT[r * 64 + ((tx ^ (r & 15)) << 2)] =
                make_float4(s[i][0], s[i][1], s[i][2], s[i][3]);
        }
        __syncthreads();

        #pragma unroll 4
        for (int k4 = 0; k4 < 16; k4++) {
            float4 p[4];
            #pragma unroll
            for (int i = 0; i < 4; i++) {
                int r = ty * 4 + i;
                p[i] = *(const float4*)&KT[r * 64 + ((k4 ^ (r & 15)) << 2)];
            }
            #pragma unroll
            for (int kk = 0; kk < 4; kk++) {
                float4 v = *(const float4*)&Vs[(k4 * 4 + kk) * 64 + tx * 4];
                float p0 = ((const float*)&p[0])[kk];
                float p1 = ((const float*)&p[1])[kk];
                float p2 = ((const float*)&p[2])[kk];
                float p3 = ((const float*)&p[3])[kk];
                o[0][0] += p0 * v.x; o[0][1] += p0 * v.y; o[0][2] += p0 * v.z; o[0][3] += p0 * v.w;
                o[1][0] += p1 * v.x; o[1][1] += p1 * v.y; o[1][2] += p1 * v.z; o[1][3] += p1 * v.w;
                o[2][0] += p2 * v.x; o[2][1] += p2 * v.y; o[2][2] += p2 * v.z; o[2][3] += p2 * v.w;
                o[3][0] += p3 * v.x; o[3][1] += p3 * v.y; o[3][2] += p3 * v.z; o[3][3] += p3 * v.w;
            }
        }
    }

    #pragma unroll
    for (int i = 0; i < 4; i++) {
        float inv = 1.0f / l[i];
        float4 w = make_float4(o[i][0] * inv, o[i][1] * inv,
                               o[i][2] * inv, o[i][3] * inv);
        *(float4*)(g_att + ((size_t)b * SEQ + q0 + ty * 4 + i) * 1024
                   + h * 64 + tx * 4) = w;
    }
}

// ---------------------------------------------------------------------------
extern "C" void kernel_launch(void* const* d_in, const int* in_sizes, int n_in,
                              void* d_out, int out_size)
{
    const float* x     = (const float*)d_in[0];
    const float* w_qkv = (const float*)d_in[1];
    const float* w_out = (const float*)d_in[2];
    for (int i = 0; i < n_in; i++) {
        if      (in_sizes[i] == M_TOK * D_MODEL)       x     = (const float*)d_in[i];
        else if (in_sizes[i] == 3 * D_MODEL * D_MODEL) w_qkv = (const float*)d_in[i];
        else if (in_sizes[i] == D_MODEL * D_MODEL)     w_out = (const float*)d_in[i];
    }
    float* out = (float*)d_out;

    float *qkv = nullptr, *att = nullptr;
    cudaGetSymbolAddress((void**)&qkv, g_qkv);
    cudaGetSymbolAddress((void**)&att, g_att);

    const int gemm_smem = 64 * 1024;
    static bool attr_set = false;
    if (!attr_set) {
        attr_set = true;
        cudaFuncSetAttribute(gemm_tf32_128x128,
                             cudaFuncAttributeMaxDynamicSharedMemorySize, gemm_smem);
    }

    // 1) QKV projection (tf32 tensor core, hi/lo split)
    gemm_tf32_128x128<<<dim3(3 * D_MODEL / 128, M_TOK / 128), 256, gemm_smem>>>(
        x, w_qkv, qkv, M_TOK, 3 * D_MODEL, D_MODEL);

    // 2) Sign-flipped NeoX RoPE
    rope_kernel<<<(M_TOK * 2 * N_HEADS * 32) / 256, 256>>>();

    // 3) Causal flash attention v3 (R9 winner)
    attn_v3<<<dim3(SEQ / 64, BATCH * N_HEADS), 256>>>();

    // 4) Output projection (tf32 tensor core)
    gemm_tf32_128x128<<<dim3(D_MODEL / 128, M_TOK / 128), 256, gemm_smem>>>(
        att, w_out, out, M_TOK, D_MODEL, D_MODEL);
}

// round 13
// speedup vs baseline: 1.1813x; 1.1621x over previous
#include <cuda_runtime.h>
#include <math.h>
#include <stdint.h>

#define D_MODEL  1024
#define N_HEADS  16
#define HEAD_DIM 64
#define BATCH    4
#define SEQ      2048
#define M_TOK    (BATCH * SEQ)   // 8192

// Scratch (allocation-free rule: __device__ globals)
__device__ float    g_qkv[(size_t)M_TOK * 3 * D_MODEL];          // 96 MB
__device__ float    g_att[(size_t)M_TOK * D_MODEL];              // 32 MB
// Packed tf32 hi/lo fragment-layout scratch
__device__ uint32_t g_xpack  [(size_t)M_TOK * D_MODEL * 2];      // 64 MB
__device__ uint32_t g_attpack[(size_t)M_TOK * D_MODEL * 2];      // 64 MB
__device__ uint32_t g_wqkvp  [(size_t)3 * D_MODEL * D_MODEL * 2];// 24 MB
__device__ uint32_t g_woutp  [(size_t)D_MODEL * D_MODEL * 2];    //  8 MB

// ---------------------------------------------------------------------------
__device__ __forceinline__ void cvt_hilo(float f, uint32_t& hi, uint32_t& lo)
{
    asm("cvt.rna.tf32.f32 %0, %1;" : "=r"(hi) : "f"(f));
    float r = f - __uint_as_float(hi);
    asm("cvt.rna.tf32.f32 %0, %1;" : "=r"(lo) : "f"(r));
}

// Pack A-operand (row-major [M][1024]) into per-(rowTile,chunk) fragment order.
// chunk = 8192 words: [0..4095]=hi frags, [4096..8191]=lo frags.
// off = ((mt*4+ks)*32 + lane)*4 + reg   (m16n8k8 A layout, verified R11)
__global__ __launch_bounds__(256) void pack_a_tf32(
    const float* __restrict__ src, uint32_t* __restrict__ dst)
{
    size_t idx = (size_t)blockIdx.x * 256 + threadIdx.x;  // one float4 each
    int row  = (int)(idx >> 8);          // K/4 = 256 groups per row
    int c4   = (int)(idx & 255) * 4;
    float4 v = *(const float4*)(src + (size_t)row * 1024 + c4);

    int rowTile = row >> 7, rowIn = row & 127;
    int chunk = c4 >> 5, c4in = c4 & 31;
    int mt = rowIn >> 4, ri = rowIn & 15;
    int ks = c4in >> 3;
    int rb = ((ri >> 3) & 1) + (((c4in & 7) >= 4) ? 2 : 0);
    int lb = (ri & 7) * 4;
    size_t base = ((size_t)rowTile * 32 + chunk) * 8192;
    float vv[4] = {v.x, v.y, v.z, v.w};
    #pragma unroll
    for (int j = 0; j < 4; j++) {
        uint32_t hi, lo;
        cvt_hilo(vv[j], hi, lo);
        int off = ((mt * 4 + ks) * 32 + lb + j) * 4 + rb;
        dst[base + off]        = hi;
        dst[base + 4096 + off] = lo;
    }
}

// Pack B-operand (W row-major [N][1024]) into fragment order.
// off = ((nt*4+ks)*32 + nin*4 + j)*2 + rg   (m16n8k8 B layout, verified R11)
__global__ __launch_bounds__(256) void pack_b_tf32(
    const float* __restrict__ src, uint32_t* __restrict__ dst)
{
    size_t idx = (size_t)blockIdx.x * 256 + threadIdx.x;
    int n   = (int)(idx >> 8);
    int k4  = (int)(idx & 255) * 4;
    float4 v = *(const float4*)(src + (size_t)n * 1024 + k4);

    int nTile = n >> 7, nIn = n & 127;
    int chunk = k4 >> 5, k4in = k4 & 31;
    int nt = nIn >> 3, nin = nIn & 7;
    int ks = k4in >> 3;
    int rg = ((k4in & 7) >= 4) ? 1 : 0;
    size_t base = ((size_t)nTile * 32 + chunk) * 8192;
    float vv[4] = {v.x, v.y, v.z, v.w};
    #pragma unroll
    for (int j = 0; j < 4; j++) {
        uint32_t hi, lo;
        cvt_hilo(vv[j], hi, lo);
        int off = ((nt * 4 + ks) * 32 + nin * 4 + j) * 2 + rg;
        dst[base + off]        = hi;
        dst[base + 4096 + off] = lo;
    }
}

// ---------------------------------------------------------------------------
// TF32 GEMM v2: packed operands, cp.async double-buffered, 3-pass hi/lo.
// C[M,N] = A[M,K] @ W[N,K]^T, tiles 128x128, BK=32, 256 thr, warp grid 2x4.
// ---------------------------------------------------------------------------
#define MMA_TF32(d, a, b)                                                    \
    asm volatile(                                                            \
        "mma.sync.aligned.m16n8k8.row.col.f32.tf32.tf32.f32 "                \
        "{%0,%1,%2,%3}, {%4,%5,%6,%7}, {%8,%9}, {%0,%1,%2,%3};"              \
        : "+f"(d[0]), "+f"(d[1]), "+f"(d[2]), "+f"(d[3])                     \
        : "r"(a[0]), "r"(a[1]), "r"(a[2]), "r"(a[3]), "r"(b[0]), "r"(b[1]))

__device__ __forceinline__ void cp16(uint32_t saddr, const uint32_t* g)
{
    asm volatile("cp.async.cg.shared.global [%0], [%1], 16;"
                 :: "r"(saddr), "l"(g));
}

extern __shared__ uint32_t gsm2[];
__global__ __launch_bounds__(256) void gemm_tf32_v2(
    const uint32_t* __restrict__ Apack, const uint32_t* __restrict__ Bpack,
    float* __restrict__ C, int M, int N, int K)
{
    const int tid  = threadIdx.x;
    const int wid  = tid >> 5;
    const int lane = tid & 31;
    const int wm   = wid & 1;
    const int wn   = wid >> 1;
    const int nch  = K >> 5;

    const uint32_t* Asrc = Apack + (size_t)blockIdx.y * nch * 8192;
    const uint32_t* Bsrc = Bpack + (size_t)blockIdx.x * nch * 8192;
    const uint32_t sbase = (uint32_t)__cvta_generic_to_shared(gsm2);

    float acc[4][4][4];
    #pragma unroll
    for (int mt = 0; mt < 4; mt++)
        #pragma unroll
        for (int nt = 0; nt < 4; nt++)
            #pragma unroll
            for (int r = 0; r < 4; r++) acc[mt][nt][r] = 0.f;

    // stage chunk 0 into buf 0
    {
        uint32_t sb = sbase;
        #pragma unroll
        for (int i = 0; i < 8; i++)
            cp16(sb + (i * 256 + tid) * 16, Asrc + (i * 256 + tid) * 4);
        #pragma unroll
        for (int i = 0; i < 8; i++)
            cp16(sb + 32768 + (i * 256 + tid) * 16, Bsrc + (i * 256 + tid) * 4);
        asm volatile("cp.async.commit_group;");
    }

    for (int c = 0; c < nch; c++) {
        __syncthreads();   // all warps done computing chunk c-1 (buf being refilled)
        if (c + 1 < nch) {
            uint32_t sb = sbase + ((c + 1) & 1) * 65536;
            const uint32_t* As = Asrc + (size_t)(c + 1) * 8192;
            #pragma unroll
            for (int i = 0; i < 8; i++)
                cp16(sb + (i * 256 + tid) * 16, As + (i * 256 + tid) * 4);
            const uint32_t* Bs = Bsrc + (size_t)(c + 1) * 8192;
            #pragma unroll
            for (int i = 0; i < 8; i++)
                cp16(sb + 32768 + (i * 256 + tid) * 16, Bs + (i * 256 + tid) * 4);
            asm volatile("cp.async.commit_group;");
            asm volatile("cp.async.wait_group 1;" ::: "memory");
        } else {
            asm volatile("cp.async.wait_group 0;" ::: "memory");
        }
        __syncthreads();   // chunk c visible to all warps

        const uint32_t* buf = gsm2 + (c & 1) * 16384;
        const uint32_t* AsH = buf;
        const uint32_t* AsL = buf + 4096;
        const uint32_t* BsH = buf + 8192;
        const uint32_t* BsL = buf + 12288;

        #pragma unroll
        for (int ks = 0; ks < 4; ks++) {
            uint32_t bh[4][2], bl[4][2];
            #pragma unroll
            for (int nt = 0; nt < 4; nt++) {
                int off = (((wn * 4 + nt) * 4 + ks) * 32 + lane) * 2;
                uint2 h = *(const uint2*)&BsH[off];
                uint2 l = *(const uint2*)&BsL[off];
                bh[nt][0] = h.x; bh[nt][1] = h.y;
                bl[nt][0] = l.x; bl[nt][1] = l.y;
            }
            #pragma unroll
            for (int mt = 0; mt < 4; mt++) {
                int off = (((wm * 4 + mt) * 4 + ks) * 32 + lane) * 4;
                uint4 h = *(const uint4*)&AsH[off];
                uint4 l = *(const uint4*)&AsL[off];
                uint32_t ah[4] = {h.x, h.y, h.z, h.w};
                uint32_t al[4] = {l.x, l.y, l.z, l.w};
                #pragma unroll
                for (int nt = 0; nt < 4; nt++) {
                    MMA_TF32(acc[mt][nt], ah, bh[nt]);
                    MMA_TF32(acc[mt][nt], al, bh[nt]);
                    MMA_TF32(acc[mt][nt], ah, bl[nt]);
                }
            }
        }
    }

    const size_t arow0 = (size_t)blockIdx.y * 128;
    const size_t brow0 = (size_t)blockIdx.x * 128;
    #pragma unroll
    for (int mt = 0; mt < 4; mt++) {
        size_t row = arow0 + wm * 64 + mt * 16 + (lane >> 2);
        #pragma unroll
        for (int nt = 0; nt < 4; nt++) {
            size_t col = brow0 + wn * 32 + nt * 8 + (lane & 3) * 2;
            *(float2*)(C + row * N + col) =
                make_float2(acc[mt][nt][0], acc[mt][nt][1]);
            *(float2*)(C + (row + 8) * N + col) =
                make_float2(acc[mt][nt][2], acc[mt][nt][3]);
        }
    }
}

// ---------------------------------------------------------------------------
// RoPE in-place, sign-flipped NeoX (decoded R6, verified R7).
// ---------------------------------------------------------------------------
__global__ __launch_bounds__(256) void rope_kernel()
{
    int idx = blockIdx.x * blockDim.x + threadIdx.x;
    int i   = idx & 31;
    int h   = (idx >> 5) & 15;
    int qk  = (idx >> 9) & 1;
    int tok = idx >> 10;
    int t   = tok & (SEQ - 1);

    double th = pow(10000.0, -(double)i / 32.0);
    float  f  = (float)t * (float)th;
    double cd, sd;
    sincos((double)f, &cd, &sd);
    float c = (float)cd, s = (float)sd;

    float* base = g_qkv + (size_t)tok * 3072 + qk * 1024 + h * 64 + i;
    float x1 = base[0];
    float x2 = base[32];
    base[0]  = x1 * c + x2 * s;
    base[32] = x2 * c - x1 * s;
}

// ---------------------------------------------------------------------------
// Flash attention v3 (R9 winner) — XOR-swizzled smem, conflict-free hot loops.
// ---------------------------------------------------------------------------
__global__ __launch_bounds__(256) void attn_v3()
{
    __shared__ float Qs[64 * 64];
    __shared__ float KT[64 * 64];
    __shared__ float Vs[64 * 64];

    const int tid = threadIdx.x;
    const int tx  = tid & 15;
    const int ty  = tid >> 4;
    const int bx  = gridDim.x - 1 - blockIdx.x;
    const int bh  = blockIdx.y;
    const int b   = bh >> 4;
    const int h   = bh & 15;
    const int q0  = bx * 64;
    const size_t base = (size_t)b * SEQ * 3072;

    #pragma unroll
    for (int i = 0; i < 4; i++) {
        int idx = tid + i * 256;
        int r   = idx >> 4;
        int d4  = (idx & 15) * 4;
        float4 v = *(const float4*)(g_qkv + base + (size_t)(q0 + r) * 3072 + h * 64 + d4);
        int rg = r >> 2, rw = r & 3;
        Qs[(d4 + 0) * 64 + ((rg ^ ((d4 + 0) & 15)) << 2) + rw] = v.x;
        Qs[(d4 + 1) * 64 + ((rg ^ ((d4 + 1) & 15)) << 2) + rw] = v.y;
        Qs[(d4 + 2) * 64 + ((rg ^ ((d4 + 2) & 15)) << 2) + rw] = v.z;
        Qs[(d4 + 3) * 64 + ((rg ^ ((d4 + 3) & 15)) << 2) + rw] = v.w;
    }

    float o[4][4];
    float m[4], l[4];
    #pragma unroll
    for (int i = 0; i < 4; i++) {
        m[i] = -1e30f; l[i] = 0.f;
        #pragma unroll
        for (int j = 0; j < 4; j++) o[i][j] = 0.f;
    }

    for (int kb = 0; kb <= bx; kb++) {
        const int j0 = kb * 64;
        __syncthreads();

        #pragma unroll
        for (int i = 0; i < 4; i++) {
            int idx = tid + i * 256;
            int c   = idx >> 4;
            int d4  = (idx & 15) * 4;
            const float* kp = g_qkv + base + (size_t)(j0 + c) * 3072 + 1024 + h * 64 + d4;
            float4 kv = *(const float4*)kp;
            float4 vv = *(const float4*)(kp + 1024);
            *(float4*)&Vs[c * 64 + d4] = vv;
            int cg = c >> 2, cw = c & 3;
            KT[(d4 + 0) * 64 + ((cg ^ ((d4 + 0) & 15)) << 2) + cw] = kv.x;
            KT[(d4 + 1) * 64 + ((cg ^ ((d4 + 1) & 15)) << 2) + cw] = kv.y;
            KT[(d4 + 2) * 64 + ((cg ^ ((d4 + 2) & 15)) << 2) + cw] = kv.z;
            KT[(d4 + 3) * 64 + ((cg ^ ((d4 + 3) & 15)) << 2) + cw] = kv.w;
        }
        __syncthreads();

        float s[4][4];
        #pragma unroll
        for (int i = 0; i < 4; i++)
            #pragma unroll
            for (int j = 0; j < 4; j++) s[i][j] = 0.f;

        #pragma unroll 16
        for (int d = 0; d < 64; d++) {
            int sw = (d & 15);
            float4 a = *(const float4*)&Qs[d * 64 + ((ty ^ sw) << 2)];
            float4 k = *(const float4*)&KT[d * 64 + ((tx ^ sw) << 2)];
            s[0][0] += a.x * k.x; s[0][1] += a.x * k.y; s[0][2] += a.x * k.z; s[0][3] += a.x * k.w;
            s[1][0] += a.y * k.x; s[1][1] += a.y * k.y; s[1][2] += a.y * k.z; s[1][3] += a.y * k.w;
            s[2][0] += a.z * k.x; s[2][1] += a.z * k.y; s[2][2] += a.z * k.z; s[2][3] += a.z * k.w;
            s[3][0] += a.w * k.x; s[3][1] += a.w * k.y; s[3][2] += a.w * k.z; s[3][3] += a.w * k.w;
        }

        if (kb == bx) {
            #pragma unroll
            for (int i = 0; i < 4; i++)
                #pragma unroll
                for (int j = 0; j < 4; j++)
                    s[i][j] = (tx * 4 + j <= ty * 4 + i) ? s[i][j] * 0.125f : -1e30f;
        } else {
            #pragma unroll
            for (int i = 0; i < 4; i++)
                #pragma unroll
                for (int j = 0; j < 4; j++) s[i][j] *= 0.125f;
        }

        float alpha[4];
        #pragma unroll
        for (int i = 0; i < 4; i++) {
            float rm = fmaxf(fmaxf(s[i][0], s[i][1]), fmaxf(s[i][2], s[i][3]));
            #pragma unroll
            for (int off = 8; off > 0; off >>= 1)
                rm = fmaxf(rm, __shfl_xor_sync(0xffffffffu, rm, off));
            float m_new = fmaxf(m[i], rm);
            alpha[i] = __expf(m[i] - m_new);
            m[i] = m_new;
            #pragma unroll
            for (int j = 0; j < 4; j++) s[i][j] = __expf(s[i][j] - m_new);
            float rl = s[i][0] + s[i][1] + s[i][2] + s[i][3];
            #pragma unroll
            for (int off = 8; off > 0; off >>= 1)
                rl += __shfl_xor_sync(0xffffffffu, rl, off);
            l[i] = l[i] * alpha[i] + rl;
            #pragma unroll
            for (int j = 0; j < 4; j++) o[i][j] *= alpha[i];
        }

        __syncthreads();

        #pragma unroll
        for (int i = 0; i < 4; i++) {
            int r = ty * 4 + i;
            *(float4*)&KT[r * 64 + ((tx ^ (r & 15)) << 2)] =
                make_float4(s[i][0], s[i][1], s[i][2], s[i][3]);
        }
        __syncthreads();

        #pragma unroll 4
        for (int k4 = 0; k4 < 16; k4++) {
            float4 p[4];
            #pragma unroll
            for (int i = 0; i < 4; i++) {
                int r = ty * 4 + i;
                p[i] = *(const float4*)&KT[r * 64 + ((k4 ^ (r & 15)) << 2)];
            }
            #pragma unroll
            for (int kk = 0; kk < 4; kk++) {
                float4 v = *(const float4*)&Vs[(k4 * 4 + kk) * 64 + tx * 4];
                float p0 = ((const float*)&p[0])[kk];
                float p1 = ((const float*)&p[1])[kk];
                float p2 = ((const float*)&p[2])[kk];
                float p3 = ((const float*)&p[3])[kk];
                o[0][0] += p0 * v.x; o[0][1] += p0 * v.y; o[0][2] += p0 * v.z; o[0][3] += p0 * v.w;
                o[1][0] += p1 * v.x; o[1][1] += p1 * v.y; o[1][2] += p1 * v.z; o[1][3] += p1 * v.w;
                o[2][0] += p2 * v.x; o[2][1] += p2 * v.y; o[2][2] += p2 * v.z; o[2][3] += p2 * v.w;
                o[3][0] += p3 * v.x; o[3][1] += p3 * v.y; o[3][2] += p3 * v.z; o[3][3] += p3 * v.w;
            }
        }
    }

    #pragma unroll
    for (int i = 0; i < 4; i++) {
        float inv = 1.0f / l[i];
        float4 w = make_float4(o[i][0] * inv, o[i][1] * inv,
                               o[i][2] * inv, o[i][3] * inv);
        *(float4*)(g_att + ((size_t)b * SEQ + q0 + ty * 4 + i) * 1024
                   + h * 64 + tx * 4) = w;
    }
}

// ---------------------------------------------------------------------------
extern "C" void kernel_launch(void* const* d_in, const int* in_sizes, int n_in,
                              void* d_out, int out_size)
{
    const float* x     = (const float*)d_in[0];
    const float* w_qkv = (const float*)d_in[1];
    const float* w_out = (const float*)d_in[2];
    for (int i = 0; i < n_in; i++) {
        if      (in_sizes[i] == M_TOK * D_MODEL)       x     = (const float*)d_in[i];
        else if (in_sizes[i] == 3 * D_MODEL * D_MODEL) w_qkv = (const float*)d_in[i];
        else if (in_sizes[i] == D_MODEL * D_MODEL)     w_out = (const float*)d_in[i];
    }
    float* out = (float*)d_out;

    float *qkv = nullptr, *att = nullptr;
    uint32_t *xp = nullptr, *ap = nullptr, *wqp = nullptr, *wop = nullptr;
    cudaGetSymbolAddress((void**)&qkv, g_qkv);
    cudaGetSymbolAddress((void**)&att, g_att);
    cudaGetSymbolAddress((void**)&xp,  g_xpack);
    cudaGetSymbolAddress((void**)&ap,  g_attpack);
    cudaGetSymbolAddress((void**)&wqp, g_wqkvp);
    cudaGetSymbolAddress((void**)&wop, g_woutp);

    const int gemm_smem = 128 * 1024;
    static bool attr_set = false;
    if (!attr_set) {
        attr_set = true;
        cudaFuncSetAttribute(gemm_tf32_v2,
                             cudaFuncAttributeMaxDynamicSharedMemorySize, gemm_smem);
    }

    // 0) Pack inputs/weights to tf32 hi/lo fragment layout
    pack_a_tf32<<<(M_TOK * 1024 / 4) / 256, 256>>>(x, xp);
    pack_b_tf32<<<(3 * D_MODEL * 1024 / 4) / 256, 256>>>(w_qkv, wqp);
    pack_b_tf32<<<(D_MODEL * 1024 / 4) / 256, 256>>>(w_out, wop);

    // 1) QKV projection (packed tf32, double-buffered cp.async)
    gemm_tf32_v2<<<dim3(3 * D_MODEL / 128, M_TOK / 128), 256, gemm_smem>>>(
        xp, wqp, qkv, M_TOK, 3 * D_MODEL, D_MODEL);

    // 2) Sign-flipped NeoX RoPE
    rope_kernel<<<(M_TOK * 2 * N_HEADS * 32) / 256, 256>>>();

    // 3) Causal flash attention v3
    attn_v3<<<dim3(SEQ / 64, BATCH * N_HEADS), 256>>>();

    // 3b) Pack attention output for the out-projection
    pack_a_tf32<<<(M_TOK * 1024 / 4) / 256, 256>>>(att, ap);

    // 4) Output projection
    gemm_tf32_v2<<<dim3(D_MODEL / 128, M_TOK / 128), 256, gemm_smem>>>(
        ap, wop, out, M_TOK, D_MODEL, D_MODEL);
}

// round 14
// speedup vs baseline: 1.3388x; 1.1333x over previous
#include <cuda_runtime.h>
#include <math.h>
#include <stdint.h>

#define D_MODEL  1024
#define N_HEADS  16
#define HEAD_DIM 64
#define BATCH    4
#define SEQ      2048
#define M_TOK    (BATCH * SEQ)   // 8192

// Scratch (allocation-free rule: __device__ globals)
__device__ float    g_qkv[(size_t)M_TOK * 3 * D_MODEL];          // 96 MB
__device__ float    g_att[(size_t)M_TOK * D_MODEL];              // 32 MB
__device__ uint32_t g_xpack  [(size_t)M_TOK * D_MODEL * 2];      // 64 MB (x pack, then Q frags)
__device__ uint32_t g_attpack[(size_t)M_TOK * D_MODEL * 2];      // 64 MB (K frags, then att pack)
__device__ uint32_t g_vpack  [(size_t)M_TOK * D_MODEL * 2];      // 64 MB (V frags)
__device__ uint32_t g_wqkvp  [(size_t)3 * D_MODEL * D_MODEL * 2];// 24 MB
__device__ uint32_t g_woutp  [(size_t)D_MODEL * D_MODEL * 2];    //  8 MB

// ---------------------------------------------------------------------------
__device__ __forceinline__ void cvt_hilo(float f, uint32_t& hi, uint32_t& lo)
{
    asm("cvt.rna.tf32.f32 %0, %1;" : "=r"(hi) : "f"(f));
    float r = f - __uint_as_float(hi);
    asm("cvt.rna.tf32.f32 %0, %1;" : "=r"(lo) : "f"(r));
}

#define MMA_TF32(d, a, b)                                                    \
    asm volatile(                                                            \
        "mma.sync.aligned.m16n8k8.row.col.f32.tf32.tf32.f32 "                \
        "{%0,%1,%2,%3}, {%4,%5,%6,%7}, {%8,%9}, {%0,%1,%2,%3};"              \
        : "+f"(d[0]), "+f"(d[1]), "+f"(d[2]), "+f"(d[3])                     \
        : "r"(a[0]), "r"(a[1]), "r"(a[2]), "r"(a[3]), "r"(b[0]), "r"(b[1]))

__device__ __forceinline__ void cp16(uint32_t saddr, const uint32_t* g)
{
    asm volatile("cp.async.cg.shared.global [%0], [%1], 16;"
                 :: "r"(saddr), "l"(g));
}

// ---------------------------------------------------------------------------
// GEMM packs (verified R11/R13)
// ---------------------------------------------------------------------------
__global__ __launch_bounds__(256) void pack_a_tf32(
    const float* __restrict__ src, uint32_t* __restrict__ dst)
{
    size_t idx = (size_t)blockIdx.x * 256 + threadIdx.x;
    int row  = (int)(idx >> 8);
    int c4   = (int)(idx & 255) * 4;
    float4 v = *(const float4*)(src + (size_t)row * 1024 + c4);

    int rowTile = row >> 7, rowIn = row & 127;
    int chunk = c4 >> 5, c4in = c4 & 31;
    int mt = rowIn >> 4, ri = rowIn & 15;
    int ks = c4in >> 3;
    int rb = ((ri >> 3) & 1) + (((c4in & 7) >= 4) ? 2 : 0);
    int lb = (ri & 7) * 4;
    size_t base = ((size_t)rowTile * 32 + chunk) * 8192;
    float vv[4] = {v.x, v.y, v.z, v.w};
    #pragma unroll
    for (int j = 0; j < 4; j++) {
        uint32_t hi, lo;
        cvt_hilo(vv[j], hi, lo);
        int off = ((mt * 4 + ks) * 32 + lb + j) * 4 + rb;
        dst[base + off]        = hi;
        dst[base + 4096 + off] = lo;
    }
}

__global__ __launch_bounds__(256) void pack_b_tf32(
    const float* __restrict__ src, uint32_t* __restrict__ dst)
{
    size_t idx = (size_t)blockIdx.x * 256 + threadIdx.x;
    int n   = (int)(idx >> 8);
    int k4  = (int)(idx & 255) * 4;
    float4 v = *(const float4*)(src + (size_t)n * 1024 + k4);

    int nTile = n >> 7, nIn = n & 127;
    int chunk = k4 >> 5, k4in = k4 & 31;
    int nt = nIn >> 3, nin = nIn & 7;
    int ks = k4in >> 3;
    int rg = ((k4in & 7) >= 4) ? 1 : 0;
    size_t base = ((size_t)nTile * 32 + chunk) * 8192;
    float vv[4] = {v.x, v.y, v.z, v.w};
    #pragma unroll
    for (int j = 0; j < 4; j++) {
        uint32_t hi, lo;
        cvt_hilo(vv[j], hi, lo);
        int off = ((nt * 4 + ks) * 32 + nin * 4 + j) * 2 + rg;
        dst[base + off]        = hi;
        dst[base + 4096 + off] = lo;
    }
}

// ---------------------------------------------------------------------------
// TF32 GEMM v2 (verified R13)
// ---------------------------------------------------------------------------
extern __shared__ uint32_t gsm2[];
__global__ __launch_bounds__(256) void gemm_tf32_v2(
    const uint32_t* __restrict__ Apack, const uint32_t* __restrict__ Bpack,
    float* __restrict__ C, int M, int N, int K)
{
    const int tid  = threadIdx.x;
    const int wid  = tid >> 5;
    const int lane = tid & 31;
    const int wm   = wid & 1;
    const int wn   = wid >> 1;
    const int nch  = K >> 5;

    const uint32_t* Asrc = Apack + (size_t)blockIdx.y * nch * 8192;
    const uint32_t* Bsrc = Bpack + (size_t)blockIdx.x * nch * 8192;
    const uint32_t sbase = (uint32_t)__cvta_generic_to_shared(gsm2);

    float acc[4][4][4];
    #pragma unroll
    for (int mt = 0; mt < 4; mt++)
        #pragma unroll
        for (int nt = 0; nt < 4; nt++)
            #pragma unroll
            for (int r = 0; r < 4; r++) acc[mt][nt][r] = 0.f;

    {
        uint32_t sb = sbase;
        #pragma unroll
        for (int i = 0; i < 8; i++)
            cp16(sb + (i * 256 + tid) * 16, Asrc + (i * 256 + tid) * 4);
        #pragma unroll
        for (int i = 0; i < 8; i++)
            cp16(sb + 32768 + (i * 256 + tid) * 16, Bsrc + (i * 256 + tid) * 4);
        asm volatile("cp.async.commit_group;");
    }

    for (int c = 0; c < nch; c++) {
        __syncthreads();
        if (c + 1 < nch) {
            uint32_t sb = sbase + ((c + 1) & 1) * 65536;
            const uint32_t* As = Asrc + (size_t)(c + 1) * 8192;
            #pragma unroll
            for (int i = 0; i < 8; i++)
                cp16(sb + (i * 256 + tid) * 16, As + (i * 256 + tid) * 4);
            const uint32_t* Bs = Bsrc + (size_t)(c + 1) * 8192;
            #pragma unroll
            for (int i = 0; i < 8; i++)
                cp16(sb + 32768 + (i * 256 + tid) * 16, Bs + (i * 256 + tid) * 4);
            asm volatile("cp.async.commit_group;");
            asm volatile("cp.async.wait_group 1;" ::: "memory");
        } else {
            asm volatile("cp.async.wait_group 0;" ::: "memory");
        }
        __syncthreads();

        const uint32_t* buf = gsm2 + (c & 1) * 16384;
        const uint32_t* AsH = buf;
        const uint32_t* AsL = buf + 4096;
        const uint32_t* BsH = buf + 8192;
        const uint32_t* BsL = buf + 12288;

        #pragma unroll
        for (int ks = 0; ks < 4; ks++) {
            uint32_t bh[4][2], bl[4][2];
            #pragma unroll
            for (int nt = 0; nt < 4; nt++) {
                int off = (((wn * 4 + nt) * 4 + ks) * 32 + lane) * 2;
                uint2 h = *(const uint2*)&BsH[off];
                uint2 l = *(const uint2*)&BsL[off];
                bh[nt][0] = h.x; bh[nt][1] = h.y;
                bl[nt][0] = l.x; bl[nt][1] = l.y;
            }
            #pragma unroll
            for (int mt = 0; mt < 4; mt++) {
                int off = (((wm * 4 + mt) * 4 + ks) * 32 + lane) * 4;
                uint4 h = *(const uint4*)&AsH[off];
                uint4 l = *(const uint4*)&AsL[off];
                uint32_t ah[4] = {h.x, h.y, h.z, h.w};
                uint32_t al[4] = {l.x, l.y, l.z, l.w};
                #pragma unroll
                for (int nt = 0; nt < 4; nt++) {
                    MMA_TF32(acc[mt][nt], ah, bh[nt]);
                    MMA_TF32(acc[mt][nt], al, bh[nt]);
                    MMA_TF32(acc[mt][nt], ah, bl[nt]);
                }
            }
        }
    }

    const size_t arow0 = (size_t)blockIdx.y * 128;
    const size_t brow0 = (size_t)blockIdx.x * 128;
    #pragma unroll
    for (int mt = 0; mt < 4; mt++) {
        size_t row = arow0 + wm * 64 + mt * 16 + (lane >> 2);
        #pragma unroll
        for (int nt = 0; nt < 4; nt++) {
            size_t col = brow0 + wn * 32 + nt * 8 + (lane & 3) * 2;
            *(float2*)(C + row * N + col) =
                make_float2(acc[mt][nt][0], acc[mt][nt][1]);
            *(float2*)(C + (row + 8) * N + col) =
                make_float2(acc[mt][nt][2], acc[mt][nt][3]);
        }
    }
}

// ---------------------------------------------------------------------------
// RoPE in-place, sign-flipped NeoX (decoded R6, verified R7).
// ---------------------------------------------------------------------------
__global__ __launch_bounds__(256) void rope_kernel()
{
    int idx = blockIdx.x * blockDim.x + threadIdx.x;
    int i   = idx & 31;
    int h   = (idx >> 5) & 15;
    int qk  = (idx >> 9) & 1;
    int tok = idx >> 10;
    int t   = tok & (SEQ - 1);

    double th = pow(10000.0, -(double)i / 32.0);
    float  f  = (float)t * (float)th;
    double cd, sd;
    sincos((double)f, &cd, &sd);
    float c = (float)cd, s = (float)sd;

    float* base = g_qkv + (size_t)tok * 3072 + qk * 1024 + h * 64 + i;
    float x1 = base[0];
    float x2 = base[32];
    base[0]  = x1 * c + x2 * s;
    base[32] = x2 * c - x1 * s;
}

// ---------------------------------------------------------------------------
// Attention packs (warp per fragment block, coalesced stores).
// Q A-frag per (bh, qt): word = (mt*8+ks)*128 + lane*4 + reg; hi | lo(+8192).
//   element(lane,reg): ri = (lane>>2)+8*(reg&1); k = ks*8+(lane&3)+4*(reg>>1)
// ---------------------------------------------------------------------------
__global__ __launch_bounds__(256) void pack_q_tc(uint32_t* __restrict__ Qp)
{
    int gw   = blockIdx.x * 8 + (threadIdx.x >> 5);   // 65536 warps
    int lane = threadIdx.x & 31;
    int ks = gw & 7, mt = (gw >> 3) & 7, qt = (gw >> 6) & 15, bh = gw >> 10;
    int b = bh >> 4, h = bh & 15;

    uint32_t hi[4], lo[4];
    #pragma unroll
    for (int r = 0; r < 4; r++) {
        int ri = (lane >> 2) + 8 * (r & 1);
        int k  = ks * 8 + (lane & 3) + 4 * (r >> 1);
        size_t tok = (size_t)b * SEQ + qt * 128 + mt * 16 + ri;
        float v = g_qkv[tok * 3072 + h * 64 + k];
        cvt_hilo(v, hi[r], lo[r]);
    }
    uint32_t* base = Qp + ((size_t)bh * 16 + qt) * 16384;
    int word = (mt * 8 + ks) * 128 + lane * 4;
    *(uint4*)(base + word)        = make_uint4(hi[0], hi[1], hi[2], hi[3]);
    *(uint4*)(base + 8192 + word) = make_uint4(lo[0], lo[1], lo[2], lo[3]);
}

// K B-frag per (bh, kt): word = (nt*8+ks)*64 + lane*2 + reg; hi | lo(+4096).
//   K element(lane,reg): n = c = nt*8+(lane>>2); k = ks*8+(lane&3)+4*reg
// V B-frag (transposed): n = d = nt*8+(lane>>2); k = c = ks*8+(lane&3)+4*reg
__global__ __launch_bounds__(256) void pack_kv_tc(
    uint32_t* __restrict__ Kp, uint32_t* __restrict__ Vp)
{
    int gw   = blockIdx.x * 8 + (threadIdx.x >> 5);   // 131072 warps
    int lane = threadIdx.x & 31;
    int ks = gw & 7, nt = (gw >> 3) & 7, kt = (gw >> 6) & 31, bh = gw >> 11;
    int b = bh >> 4, h = bh & 15;

    uint32_t khi[2], klo[2], vhi[2], vlo[2];
    #pragma unroll
    for (int r = 0; r < 2; r++) {
        // K
        {
            int c = kt * 64 + nt * 8 + (lane >> 2);
            int k = ks * 8 + (lane & 3) + 4 * r;
            size_t tok = (size_t)b * SEQ + c;
            float v = g_qkv[tok * 3072 + 1024 + h * 64 + k];
            cvt_hilo(v, khi[r], klo[r]);
        }
        // V (transposed: frag n = headdim, frag k = key row)
        {
            int d = nt * 8 + (lane >> 2);
            int c = ks * 8 + (lane & 3) + 4 * r;
            size_t tok = (size_t)b * SEQ + kt * 64 + c;
            float v = g_qkv[tok * 3072 + 2048 + h * 64 + d];
            cvt_hilo(v, vhi[r], vlo[r]);
        }
    }
    size_t base = ((size_t)bh * 32 + kt) * 8192;
    int word = (nt * 8 + ks) * 64 + lane * 2;
    *(uint2*)(Kp + base + word)        = make_uint2(khi[0], khi[1]);
    *(uint2*)(Kp + base + 4096 + word) = make_uint2(klo[0], klo[1]);
    *(uint2*)(Vp + base + word)        = make_uint2(vhi[0], vhi[1]);
    *(uint2*)(Vp + base + 4096 + word) = make_uint2(vlo[0], vlo[1]);
}

// ---------------------------------------------------------------------------
// Tensor-core flash attention: BQ=128 (8 warps x 16 rows), BK=64, tf32 3-pass.
// smem: QF 64KB | KV buf0 64KB | KV buf1 64KB = 192KB dynamic.
// ---------------------------------------------------------------------------
extern __shared__ uint32_t atsm[];
__global__ __launch_bounds__(256) void attn_tc(
    const uint32_t* __restrict__ Qp, const uint32_t* __restrict__ Kp,
    const uint32_t* __restrict__ Vp)
{
    const int tid  = threadIdx.x;
    const int wid  = tid >> 5;
    const int lane = tid & 31;
    const int bx   = gridDim.x - 1 - blockIdx.x;   // heavy CTAs first
    const int bh   = blockIdx.y;
    const int b    = bh >> 4;
    const int h    = bh & 15;
    const int q0   = bx * 128;
    const int nch  = 2 * (bx + 1);

    const uint32_t sbase = (uint32_t)__cvta_generic_to_shared(atsm);
    const uint32_t* Qsrc = Qp + ((size_t)bh * 16 + bx) * 16384;
    const uint32_t* Ksrc = Kp + (size_t)bh * 32 * 8192;
    const uint32_t* Vsrc = Vp + (size_t)bh * 32 * 8192;

    // stage Q (64KB) + chunk0 K,V (64KB) into buf0
    #pragma unroll
    for (int i = 0; i < 16; i++)
        cp16(sbase + (i * 256 + tid) * 16, Qsrc + (i * 256 + tid) * 4);
    #pragma unroll
    for (int i = 0; i < 8; i++)
        cp16(sbase + 65536 + (i * 256 + tid) * 16, Ksrc + (i * 256 + tid) * 4);
    #pragma unroll
    for (int i = 0; i < 8; i++)
        cp16(sbase + 65536 + 32768 + (i * 256 + tid) * 16, Vsrc + (i * 256 + tid) * 4);
    asm volatile("cp.async.commit_group;");

    float o[8][4];
    #pragma unroll
    for (int nt = 0; nt < 8; nt++)
        #pragma unroll
        for (int j = 0; j < 4; j++) o[nt][j] = 0.f;
    float m0 = -1e30f, m1 = -1e30f, l0 = 0.f, l1 = 0.f;

    const int row0 = q0 + wid * 16 + (lane >> 2);
    const int c4l  = lane & 3;
    const int idx1 = (lane & 28) | (c4l >> 1);     // lane holding col c
    const int idx2 = idx1 + 2;                     // lane holding col c+4

    for (int c = 0; c < nch; c++) {
        if (c + 1 < nch) {
            uint32_t sb = sbase + 65536 + ((c + 1) & 1) * 65536;
            const uint32_t* Ks = Ksrc + (size_t)(c + 1) * 8192;
            const uint32_t* Vs = Vsrc + (size_t)(c + 1) * 8192;
            #pragma unroll
            for (int i = 0; i < 8; i++)
                cp16(sb + (i * 256 + tid) * 16, Ks + (i * 256 + tid) * 4);
            #pragma unroll
            for (int i = 0; i < 8; i++)
                cp16(sb + 32768 + (i * 256 + tid) * 16, Vs + (i * 256 + tid) * 4);
            asm volatile("cp.async.commit_group;");
            asm volatile("cp.async.wait_group 1;" ::: "memory");
        } else {
            asm volatile("cp.async.wait_group 0;" ::: "memory");
        }
        __syncthreads();

        const uint32_t* QF = atsm;
        const uint32_t* KF = atsm + 16384 + (c & 1) * 16384;
        const uint32_t* VF = KF + 8192;

        // --- S = Q K^T (3-pass) ---
        float s[8][4];
        #pragma unroll
        for (int nt = 0; nt < 8; nt++)
            #pragma unroll
            for (int j = 0; j < 4; j++) s[nt][j] = 0.f;

        #pragma unroll
        for (int ks = 0; ks < 8; ks++) {
            uint4 qh4 = *(const uint4*)&QF[(wid * 8 + ks) * 128 + lane * 4];
            uint4 ql4 = *(const uint4*)&QF[8192 + (wid * 8 + ks) * 128 + lane * 4];
            uint32_t qh[4] = {qh4.x, qh4.y, qh4.z, qh4.w};
            uint32_t ql[4] = {ql4.x, ql4.y, ql4.z, ql4.w};
            #pragma unroll
            for (int nt = 0; nt < 8; nt++) {
                uint2 kh2 = *(const uint2*)&KF[(nt * 8 + ks) * 64 + lane * 2];
                uint2 kl2 = *(const uint2*)&KF[4096 + (nt * 8 + ks) * 64 + lane * 2];
                uint32_t kh[2] = {kh2.x, kh2.y};
                uint32_t kl[2] = {kl2.x, kl2.y};
                MMA_TF32(s[nt], qh, kh);
                MMA_TF32(s[nt], ql, kh);
                MMA_TF32(s[nt], qh, kl);
            }
        }

        // --- scale + causal mask (last two chunks only) ---
        const int j0 = c * 64;
        if (c >= 2 * bx) {
            #pragma unroll
            for (int nt = 0; nt < 8; nt++) {
                #pragma unroll
                for (int j = 0; j < 4; j++) {
                    int col = j0 + nt * 8 + c4l * 2 + (j & 1);
                    int row = (j < 2) ? row0 : row0 + 8;
                    s[nt][j] = (col <= row) ? s[nt][j] * 0.125f : -1e30f;
                }
            }
        } else {
            #pragma unroll
            for (int nt = 0; nt < 8; nt++)
                #pragma unroll
                for (int j = 0; j < 4; j++) s[nt][j] *= 0.125f;
        }

        // --- online softmax on acc layout ---
        float mt0 = -1e30f, mt1 = -1e30f;
        #pragma unroll
        for (int nt = 0; nt < 8; nt++) {
            mt0 = fmaxf(mt0, fmaxf(s[nt][0], s[nt][1]));
            mt1 = fmaxf(mt1, fmaxf(s[nt][2], s[nt][3]));
        }
        mt0 = fmaxf(mt0, __shfl_xor_sync(0xffffffffu, mt0, 1));
        mt0 = fmaxf(mt0, __shfl_xor_sync(0xffffffffu, mt0, 2));
        mt1 = fmaxf(mt1, __shfl_xor_sync(0xffffffffu, mt1, 1));
        mt1 = fmaxf(mt1, __shfl_xor_sync(0xffffffffu, mt1, 2));

        float m0n = fmaxf(m0, mt0), m1n = fmaxf(m1, mt1);
        float a0 = __expf(m0 - m0n), a1 = __expf(m1 - m1n);
        m0 = m0n; m1 = m1n;

        float lt0 = 0.f, lt1 = 0.f;
        #pragma unroll
        for (int nt = 0; nt < 8; nt++) {
            s[nt][0] = __expf(s[nt][0] - m0n);
            s[nt][1] = __expf(s[nt][1] - m0n);
            s[nt][2] = __expf(s[nt][2] - m1n);
            s[nt][3] = __expf(s[nt][3] - m1n);
            lt0 += s[nt][0] + s[nt][1];
            lt1 += s[nt][2] + s[nt][3];
        }
        lt0 += __shfl_xor_sync(0xffffffffu, lt0, 1);
        lt0 += __shfl_xor_sync(0xffffffffu, lt0, 2);
        lt1 += __shfl_xor_sync(0xffffffffu, lt1, 1);
        lt1 += __shfl_xor_sync(0xffffffffu, lt1, 2);
        l0 = l0 * a0 + lt0;
        l1 = l1 * a1 + lt1;

        #pragma unroll
        for (int nt = 0; nt < 8; nt++) {
            o[nt][0] *= a0; o[nt][1] *= a0;
            o[nt][2] *= a1; o[nt][3] *= a1;
        }

        // --- O += P V (convert P acc-frag -> A-frag via 4-lane shuffles) ---
        #pragma unroll
        for (int ks2 = 0; ks2 < 8; ks2++) {
            float v0a = __shfl_sync(0xffffffffu, s[ks2][0], idx1);
            float v0b = __shfl_sync(0xffffffffu, s[ks2][1], idx1);
            float v2a = __shfl_sync(0xffffffffu, s[ks2][0], idx2);
            float v2b = __shfl_sync(0xffffffffu, s[ks2][1], idx2);
            float v1a = __shfl_sync(0xffffffffu, s[ks2][2], idx1);
            float v1b = __shfl_sync(0xffffffffu, s[ks2][3], idx1);
            float v3a = __shfl_sync(0xffffffffu, s[ks2][2], idx2);
            float v3b = __shfl_sync(0xffffffffu, s[ks2][3], idx2);
            bool oddc = (c4l & 1);
            float af0 = oddc ? v0b : v0a;   // (row0, k=c)
            float af1 = oddc ? v1b : v1a;   // (row1, k=c)
            float af2 = oddc ? v2b : v2a;   // (row0, k=c+4)
            float af3 = oddc ? v3b : v3a;   // (row1, k=c+4)

            uint32_t pah[4], pal[4];
            cvt_hilo(af0, pah[0], pal[0]);
            cvt_hilo(af1, pah[1], pal[1]);
            cvt_hilo(af2, pah[2], pal[2]);
            cvt_hilo(af3, pah[3], pal[3]);

            #pragma unroll
            for (int nt = 0; nt < 8; nt++) {
                uint2 vh2 = *(const uint2*)&VF[(nt * 8 + ks2) * 64 + lane * 2];
                uint2 vl2 = *(const uint2*)&VF[4096 + (nt * 8 + ks2) * 64 + lane * 2];
                uint32_t vh[2] = {vh2.x, vh2.y};
                uint32_t vl[2] = {vl2.x, vl2.y};
                MMA_TF32(o[nt], pah, vh);
                MMA_TF32(o[nt], pal, vh);
                MMA_TF32(o[nt], pah, vl);
            }
        }
        __syncthreads();   // buffer (c&1) free for prefetch of chunk c+2
    }

    // --- epilogue ---
    float inv0 = 1.0f / l0, inv1 = 1.0f / l1;
    #pragma unroll
    for (int nt = 0; nt < 8; nt++) {
        int col = h * 64 + nt * 8 + c4l * 2;
        *(float2*)(g_att + ((size_t)b * SEQ + row0) * 1024 + col) =
            make_float2(o[nt][0] * inv0, o[nt][1] * inv0);
        *(float2*)(g_att + ((size_t)b * SEQ + row0 + 8) * 1024 + col) =
            make_float2(o[nt][2] * inv1, o[nt][3] * inv1);
    }
}

// ---------------------------------------------------------------------------
extern "C" void kernel_launch(void* const* d_in, const int* in_sizes, int n_in,
                              void* d_out, int out_size)
{
    const float* x     = (const float*)d_in[0];
    const float* w_qkv = (const float*)d_in[1];
    const float* w_out = (const float*)d_in[2];
    for (int i = 0; i < n_in; i++) {
        if      (in_sizes[i] == M_TOK * D_MODEL)       x     = (const float*)d_in[i];
        else if (in_sizes[i] == 3 * D_MODEL * D_MODEL) w_qkv = (const float*)d_in[i];
        else if (in_sizes[i] == D_MODEL * D_MODEL)     w_out = (const float*)d_in[i];
    }
    float* out = (float*)d_out;

    float *qkv = nullptr, *att = nullptr;
    uint32_t *xp = nullptr, *ap = nullptr, *vp = nullptr, *wqp = nullptr, *wop = nullptr;
    cudaGetSymbolAddress((void**)&qkv, g_qkv);
    cudaGetSymbolAddress((void**)&att, g_att);
    cudaGetSymbolAddress((void**)&xp,  g_xpack);
    cudaGetSymbolAddress((void**)&ap,  g_attpack);
    cudaGetSymbolAddress((void**)&vp,  g_vpack);
    cudaGetSymbolAddress((void**)&wqp, g_wqkvp);
    cudaGetSymbolAddress((void**)&wop, g_woutp);

    static bool attr_set = false;
    if (!attr_set) {
        attr_set = true;
        cudaFuncSetAttribute(gemm_tf32_v2,
                             cudaFuncAttributeMaxDynamicSharedMemorySize, 128 * 1024);
        cudaFuncSetAttribute(attn_tc,
                             cudaFuncAttributeMaxDynamicSharedMemorySize, 192 * 1024);
    }

    // 0) Pack inputs/weights for GEMMs
    pack_a_tf32<<<(M_TOK * 1024 / 4) / 256, 256>>>(x, xp);
    pack_b_tf32<<<(3 * D_MODEL * 1024 / 4) / 256, 256>>>(w_qkv, wqp);
    pack_b_tf32<<<(D_MODEL * 1024 / 4) / 256, 256>>>(w_out, wop);

    // 1) QKV projection
    gemm_tf32_v2<<<dim3(3 * D_MODEL / 128, M_TOK / 128), 256, 128 * 1024>>>(
        xp, wqp, qkv, M_TOK, 3 * D_MODEL, D_MODEL);

    // 2) Sign-flipped NeoX RoPE
    rope_kernel<<<(M_TOK * 2 * N_HEADS * 32) / 256, 256>>>();

    // 3) Pack Q/K/V into attention fragment layouts (Qp=g_xpack, Kp=g_attpack)
    pack_q_tc<<<8192, 256>>>(xp);
    pack_kv_tc<<<16384, 256>>>(ap, vp);

    // 4) Tensor-core flash attention
    attn_tc<<<dim3(SEQ / 128, BATCH * N_HEADS), 256, 192 * 1024>>>(xp, ap, vp);

    // 5) Pack attention output, then out-projection
    pack_a_tf32<<<(M_TOK * 1024 / 4) / 256, 256>>>(att, ap);
    gemm_tf32_v2<<<dim3(D_MODEL / 128, M_TOK / 128), 256, 128 * 1024>>>(
        ap, wop, out, M_TOK, D_MODEL, D_MODEL);
}

// round 15
// speedup vs baseline: 2.6478x; 1.9777x over previous
#include <cuda_runtime.h>
#include <math.h>
#include <stdint.h>

#define D_MODEL  1024
#define N_HEADS  16
#define HEAD_DIM 64
#define BATCH    4
#define SEQ      2048
#define M_TOK    (BATCH * SEQ)   // 8192

// Scratch (allocation-free rule: __device__ globals)
__device__ float    g_qkv[(size_t)M_TOK * 3 * D_MODEL];          // 96 MB; reused as attn A-frag out
__device__ uint32_t g_xpack  [(size_t)M_TOK * D_MODEL * 2];      // x pack, then Q frags
__device__ uint32_t g_attpack[(size_t)M_TOK * D_MODEL * 2];      // K frags
__device__ uint32_t g_vpack  [(size_t)M_TOK * D_MODEL * 2];      // V frags
__device__ uint32_t g_wqkvp  [(size_t)3 * D_MODEL * D_MODEL * 2];
__device__ uint32_t g_woutp  [(size_t)D_MODEL * D_MODEL * 2];
__device__ float2   g_trig[SEQ * 32];                            // (cos,sin) per (t, i)

// ---------------------------------------------------------------------------
__device__ __forceinline__ void cvt_hilo(float f, uint32_t& hi, uint32_t& lo)
{
    asm("cvt.rna.tf32.f32 %0, %1;" : "=r"(hi) : "f"(f));
    float r = f - __uint_as_float(hi);
    asm("cvt.rna.tf32.f32 %0, %1;" : "=r"(lo) : "f"(r));
}

#define MMA_TF32(d, a, b)                                                    \
    asm volatile(                                                            \
        "mma.sync.aligned.m16n8k8.row.col.f32.tf32.tf32.f32 "                \
        "{%0,%1,%2,%3}, {%4,%5,%6,%7}, {%8,%9}, {%0,%1,%2,%3};"              \
        : "+f"(d[0]), "+f"(d[1]), "+f"(d[2]), "+f"(d[3])                     \
        : "r"(a[0]), "r"(a[1]), "r"(a[2]), "r"(a[3]), "r"(b[0]), "r"(b[1]))

__device__ __forceinline__ void cp16(uint32_t saddr, const uint32_t* g)
{
    asm volatile("cp.async.cg.shared.global [%0], [%1], 16;"
                 :: "r"(saddr), "l"(g));
}

// ---------------------------------------------------------------------------
// Trig table: (cos,sin) of fl32(t * fl32(10000^(-i/32))) — matches verified rope.
// ---------------------------------------------------------------------------
__global__ __launch_bounds__(256) void trig_kernel()
{
    int idx = blockIdx.x * 256 + threadIdx.x;   // < SEQ*32
    int i = idx & 31;
    int t = idx >> 5;
    double th = pow(10000.0, -(double)i / 32.0);
    float  f  = (float)t * (float)th;
    double cd, sd;
    sincos((double)f, &cd, &sd);
    g_trig[idx] = make_float2((float)cd, (float)sd);
}

// ---------------------------------------------------------------------------
// GEMM packs (verified R11/R13)
// ---------------------------------------------------------------------------
__global__ __launch_bounds__(256) void pack_a_tf32(
    const float* __restrict__ src, uint32_t* __restrict__ dst)
{
    size_t idx = (size_t)blockIdx.x * 256 + threadIdx.x;
    int row  = (int)(idx >> 8);
    int c4   = (int)(idx & 255) * 4;
    float4 v = *(const float4*)(src + (size_t)row * 1024 + c4);

    int rowTile = row >> 7, rowIn = row & 127;
    int chunk = c4 >> 5, c4in = c4 & 31;
    int mt = rowIn >> 4, ri = rowIn & 15;
    int ks = c4in >> 3;
    int rb = ((ri >> 3) & 1) + (((c4in & 7) >= 4) ? 2 : 0);
    int lb = (ri & 7) * 4;
    size_t base = ((size_t)rowTile * 32 + chunk) * 8192;
    float vv[4] = {v.x, v.y, v.z, v.w};
    #pragma unroll
    for (int j = 0; j < 4; j++) {
        uint32_t hi, lo;
        cvt_hilo(vv[j], hi, lo);
        int off = ((mt * 4 + ks) * 32 + lb + j) * 4 + rb;
        dst[base + off]        = hi;
        dst[base + 4096 + off] = lo;
    }
}

__global__ __launch_bounds__(256) void pack_b_tf32(
    const float* __restrict__ src, uint32_t* __restrict__ dst)
{
    size_t idx = (size_t)blockIdx.x * 256 + threadIdx.x;
    int n   = (int)(idx >> 8);
    int k4  = (int)(idx & 255) * 4;
    float4 v = *(const float4*)(src + (size_t)n * 1024 + k4);

    int nTile = n >> 7, nIn = n & 127;
    int chunk = k4 >> 5, k4in = k4 & 31;
    int nt = nIn >> 3, nin = nIn & 7;
    int ks = k4in >> 3;
    int rg = ((k4in & 7) >= 4) ? 1 : 0;
    size_t base = ((size_t)nTile * 32 + chunk) * 8192;
    float vv[4] = {v.x, v.y, v.z, v.w};
    #pragma unroll
    for (int j = 0; j < 4; j++) {
        uint32_t hi, lo;
        cvt_hilo(vv[j], hi, lo);
        int off = ((nt * 4 + ks) * 32 + nin * 4 + j) * 2 + rg;
        dst[base + off]        = hi;
        dst[base + 4096 + off] = lo;
    }
}

// ---------------------------------------------------------------------------
// TF32 GEMM v2 (verified R13)
// ---------------------------------------------------------------------------
extern __shared__ uint32_t gsm2[];
__global__ __launch_bounds__(256) void gemm_tf32_v2(
    const uint32_t* __restrict__ Apack, const uint32_t* __restrict__ Bpack,
    float* __restrict__ C, int M, int N, int K)
{
    const int tid  = threadIdx.x;
    const int wid  = tid >> 5;
    const int lane = tid & 31;
    const int wm   = wid & 1;
    const int wn   = wid >> 1;
    const int nch  = K >> 5;

    const uint32_t* Asrc = Apack + (size_t)blockIdx.y * nch * 8192;
    const uint32_t* Bsrc = Bpack + (size_t)blockIdx.x * nch * 8192;
    const uint32_t sbase = (uint32_t)__cvta_generic_to_shared(gsm2);

    float acc[4][4][4];
    #pragma unroll
    for (int mt = 0; mt < 4; mt++)
        #pragma unroll
        for (int nt = 0; nt < 4; nt++)
            #pragma unroll
            for (int r = 0; r < 4; r++) acc[mt][nt][r] = 0.f;

    {
        uint32_t sb = sbase;
        #pragma unroll
        for (int i = 0; i < 8; i++)
            cp16(sb + (i * 256 + tid) * 16, Asrc + (i * 256 + tid) * 4);
        #pragma unroll
        for (int i = 0; i < 8; i++)
            cp16(sb + 32768 + (i * 256 + tid) * 16, Bsrc + (i * 256 + tid) * 4);
        asm volatile("cp.async.commit_group;");
    }

    for (int c = 0; c < nch; c++) {
        __syncthreads();
        if (c + 1 < nch) {
            uint32_t sb = sbase + ((c + 1) & 1) * 65536;
            const uint32_t* As = Asrc + (size_t)(c + 1) * 8192;
            #pragma unroll
            for (int i = 0; i < 8; i++)
                cp16(sb + (i * 256 + tid) * 16, As + (i * 256 + tid) * 4);
            const uint32_t* Bs = Bsrc + (size_t)(c + 1) * 8192;
            #pragma unroll
            for (int i = 0; i < 8; i++)
                cp16(sb + 32768 + (i * 256 + tid) * 16, Bs + (i * 256 + tid) * 4);
            asm volatile("cp.async.commit_group;");
            asm volatile("cp.async.wait_group 1;" ::: "memory");
        } else {
            asm volatile("cp.async.wait_group 0;" ::: "memory");
        }
        __syncthreads();

        const uint32_t* buf = gsm2 + (c & 1) * 16384;
        const uint32_t* AsH = buf;
        const uint32_t* AsL = buf + 4096;
        const uint32_t* BsH = buf + 8192;
        const uint32_t* BsL = buf + 12288;

        #pragma unroll
        for (int ks = 0; ks < 4; ks++) {
            uint32_t bh[4][2], bl[4][2];
            #pragma unroll
            for (int nt = 0; nt < 4; nt++) {
                int off = (((wn * 4 + nt) * 4 + ks) * 32 + lane) * 2;
                uint2 h = *(const uint2*)&BsH[off];
                uint2 l = *(const uint2*)&BsL[off];
                bh[nt][0] = h.x; bh[nt][1] = h.y;
                bl[nt][0] = l.x; bl[nt][1] = l.y;
            }
            #pragma unroll
            for (int mt = 0; mt < 4; mt++) {
                int off = (((wm * 4 + mt) * 4 + ks) * 32 + lane) * 4;
                uint4 h = *(const uint4*)&AsH[off];
                uint4 l = *(const uint4*)&AsL[off];
                uint32_t ah[4] = {h.x, h.y, h.z, h.w};
                uint32_t al[4] = {l.x, l.y, l.z, l.w};
                #pragma unroll
                for (int nt = 0; nt < 4; nt++) {
                    MMA_TF32(acc[mt][nt], ah, bh[nt]);
                    MMA_TF32(acc[mt][nt], al, bh[nt]);
                    MMA_TF32(acc[mt][nt], ah, bl[nt]);
                }
            }
        }
    }

    const size_t arow0 = (size_t)blockIdx.y * 128;
    const size_t brow0 = (size_t)blockIdx.x * 128;
    #pragma unroll
    for (int mt = 0; mt < 4; mt++) {
        size_t row = arow0 + wm * 64 + mt * 16 + (lane >> 2);
        #pragma unroll
        for (int nt = 0; nt < 4; nt++) {
            size_t col = brow0 + wn * 32 + nt * 8 + (lane & 3) * 2;
            *(float2*)(C + row * N + col) =
                make_float2(acc[mt][nt][0], acc[mt][nt][1]);
            *(float2*)(C + (row + 8) * N + col) =
                make_float2(acc[mt][nt][2], acc[mt][nt][3]);
        }
    }
}

// ---------------------------------------------------------------------------
// Fused RoPE + Q/K/V fragment pack. Grid (16 qt, 64 bh), 256 threads.
// Stages Q/K/V (128 tokens x 64 dims each) coalesced into smem, applies
// sign-flipped NeoX rope to Q,K via trig table, emits fragment layouts
// (identical formulas to verified pack_q_tc / pack_kv_tc).
// smem: 3 * 128 * 68 floats = 104448 B dynamic.
// ---------------------------------------------------------------------------
extern __shared__ float rps[];
__global__ __launch_bounds__(256) void rope_pack(
    uint32_t* __restrict__ Qp, uint32_t* __restrict__ Kp,
    uint32_t* __restrict__ Vp)
{
    const int tid  = threadIdx.x;
    const int wid  = tid >> 5;
    const int lane = tid & 31;
    const int qt   = blockIdx.x;
    const int bh   = blockIdx.y;
    const int b    = bh >> 4;
    const int h    = bh & 15;
    const int t0   = qt * 128;                    // position within sequence
    const size_t tok0 = (size_t)b * SEQ + t0;

    float* Qs = rps;
    float* Ks = rps + 128 * 68;
    float* Vs = rps + 2 * 128 * 68;

    // coalesced staging (256B rows)
    #pragma unroll
    for (int mat = 0; mat < 3; mat++) {
        float* dst = rps + mat * 128 * 68;
        const float* src = g_qkv + tok0 * 3072 + mat * 1024 + h * 64;
        #pragma unroll
        for (int i = 0; i < 8; i++) {
            int idx = tid + i * 256;
            int r   = idx >> 4;
            int d4  = (idx & 15) * 4;
            *(float4*)&dst[r * 68 + d4] = *(const float4*)(src + (size_t)r * 3072 + d4);
        }
    }
    __syncthreads();

    // rope Q,K in smem (each (r, fi) pair owned by exactly one thread)
    #pragma unroll
    for (int i = 0; i < 16; i++) {
        int idx = tid + i * 256;    // < 4096 = 128*32
        int r   = idx >> 5;
        int fi  = idx & 31;
        float2 cs = g_trig[(t0 + r) * 32 + fi];
        float x1 = Qs[r * 68 + fi], x2 = Qs[r * 68 + fi + 32];
        Qs[r * 68 + fi]      = x1 * cs.x + x2 * cs.y;
        Qs[r * 68 + fi + 32] = x2 * cs.x - x1 * cs.y;
        float y1 = Ks[r * 68 + fi], y2 = Ks[r * 68 + fi + 32];
        Ks[r * 68 + fi]      = y1 * cs.x + y2 * cs.y;
        Ks[r * 68 + fi + 32] = y2 * cs.x - y1 * cs.y;
    }
    __syncthreads();

    // emit Q A-frags (warp wid handles mt = wid)
    {
        uint32_t* base = Qp + ((size_t)bh * 16 + qt) * 16384;
        int mt = wid;
        #pragma unroll
        for (int ks = 0; ks < 8; ks++) {
            uint32_t hi[4], lo[4];
            #pragma unroll
            for (int r = 0; r < 4; r++) {
                int ri = (lane >> 2) + 8 * (r & 1);
                int k  = ks * 8 + (lane & 3) + 4 * (r >> 1);
                cvt_hilo(Qs[(mt * 16 + ri) * 68 + k], hi[r], lo[r]);
            }
            int word = (mt * 8 + ks) * 128 + lane * 4;
            *(uint4*)(base + word)        = make_uint4(hi[0], hi[1], hi[2], hi[3]);
            *(uint4*)(base + 8192 + word) = make_uint4(lo[0], lo[1], lo[2], lo[3]);
        }
    }

    // emit K,V B-frags for the two 64-token halves (warp wid handles nt = wid)
    #pragma unroll
    for (int half = 0; half < 2; half++) {
        int kt = qt * 2 + half;
        size_t basei = ((size_t)bh * 32 + kt) * 8192;
        int nt = wid;
        #pragma unroll
        for (int ks = 0; ks < 8; ks++) {
            uint32_t khi[2], klo[2], vhi[2], vlo[2];
            #pragma unroll
            for (int r = 0; r < 2; r++) {
                int c = half * 64 + nt * 8 + (lane >> 2);
                int k = ks * 8 + (lane & 3) + 4 * r;
                cvt_hilo(Ks[c * 68 + k], khi[r], klo[r]);
                int d  = nt * 8 + (lane >> 2);
                int c2 = half * 64 + ks * 8 + (lane & 3) + 4 * r;
                cvt_hilo(Vs[c2 * 68 + d], vhi[r], vlo[r]);
            }
            int word = (nt * 8 + ks) * 64 + lane * 2;
            *(uint2*)(Kp + basei + word)        = make_uint2(khi[0], khi[1]);
            *(uint2*)(Kp + basei + 4096 + word) = make_uint2(klo[0], klo[1]);
            *(uint2*)(Vp + basei + word)        = make_uint2(vhi[0], vhi[1]);
            *(uint2*)(Vp + basei + 4096 + word) = make_uint2(vlo[0], vlo[1]);
        }
    }
}

// ---------------------------------------------------------------------------
// Tensor-core flash attention (verified R14) with epilogue writing the
// out-projection A-fragments directly (normalize -> acc->A-frag shuffle ->
// cvt_hilo -> uint4), into Ap (g_qkv reused as scratch).
// ---------------------------------------------------------------------------
extern __shared__ uint32_t atsm[];
__global__ __launch_bounds__(256) void attn_tc(
    const uint32_t* __restrict__ Qp, const uint32_t* __restrict__ Kp,
    const uint32_t* __restrict__ Vp, uint32_t* __restrict__ Ap)
{
    const int tid  = threadIdx.x;
    const int wid  = tid >> 5;
    const int lane = tid & 31;
    const int bx   = gridDim.x - 1 - blockIdx.x;
    const int bh   = blockIdx.y;
    const int b    = bh >> 4;
    const int h    = bh & 15;
    const int q0   = bx * 128;
    const int nch  = 2 * (bx + 1);

    const uint32_t sbase = (uint32_t)__cvta_generic_to_shared(atsm);
    const uint32_t* Qsrc = Qp + ((size_t)bh * 16 + bx) * 16384;
    const uint32_t* Ksrc = Kp + (size_t)bh * 32 * 8192;
    const uint32_t* Vsrc = Vp + (size_t)bh * 32 * 8192;

    #pragma unroll
    for (int i = 0; i < 16; i++)
        cp16(sbase + (i * 256 + tid) * 16, Qsrc + (i * 256 + tid) * 4);
    #pragma unroll
    for (int i = 0; i < 8; i++)
        cp16(sbase + 65536 + (i * 256 + tid) * 16, Ksrc + (i * 256 + tid) * 4);
    #pragma unroll
    for (int i = 0; i < 8; i++)
        cp16(sbase + 65536 + 32768 + (i * 256 + tid) * 16, Vsrc + (i * 256 + tid) * 4);
    asm volatile("cp.async.commit_group;");

    float o[8][4];
    #pragma unroll
    for (int nt = 0; nt < 8; nt++)
        #pragma unroll
        for (int j = 0; j < 4; j++) o[nt][j] = 0.f;
    float m0 = -1e30f, m1 = -1e30f, l0 = 0.f, l1 = 0.f;

    const int row0 = q0 + wid * 16 + (lane >> 2);
    const int c4l  = lane & 3;
    const int idx1 = (lane & 28) | (c4l >> 1);
    const int idx2 = idx1 + 2;

    for (int c = 0; c < nch; c++) {
        if (c + 1 < nch) {
            uint32_t sb = sbase + 65536 + ((c + 1) & 1) * 65536;
            const uint32_t* Ks = Ksrc + (size_t)(c + 1) * 8192;
            const uint32_t* Vs = Vsrc + (size_t)(c + 1) * 8192;
            #pragma unroll
            for (int i = 0; i < 8; i++)
                cp16(sb + (i * 256 + tid) * 16, Ks + (i * 256 + tid) * 4);
            #pragma unroll
            for (int i = 0; i < 8; i++)
                cp16(sb + 32768 + (i * 256 + tid) * 16, Vs + (i * 256 + tid) * 4);
            asm volatile("cp.async.commit_group;");
            asm volatile("cp.async.wait_group 1;" ::: "memory");
        } else {
            asm volatile("cp.async.wait_group 0;" ::: "memory");
        }
        __syncthreads();

        const uint32_t* QF = atsm;
        const uint32_t* KF = atsm + 16384 + (c & 1) * 16384;
        const uint32_t* VF = KF + 8192;

        float s[8][4];
        #pragma unroll
        for (int nt = 0; nt < 8; nt++)
            #pragma unroll
            for (int j = 0; j < 4; j++) s[nt][j] = 0.f;

        #pragma unroll
        for (int ks = 0; ks < 8; ks++) {
            uint4 qh4 = *(const uint4*)&QF[(wid * 8 + ks) * 128 + lane * 4];
            uint4 ql4 = *(const uint4*)&QF[8192 + (wid * 8 + ks) * 128 + lane * 4];
            uint32_t qh[4] = {qh4.x, qh4.y, qh4.z, qh4.w};
            uint32_t ql[4] = {ql4.x, ql4.y, ql4.z, ql4.w};
            #pragma unroll
            for (int nt = 0; nt < 8; nt++) {
                uint2 kh2 = *(const uint2*)&KF[(nt * 8 + ks) * 64 + lane * 2];
                uint2 kl2 = *(const uint2*)&KF[4096 + (nt * 8 + ks) * 64 + lane * 2];
                uint32_t kh[2] = {kh2.x, kh2.y};
                uint32_t kl[2] = {kl2.x, kl2.y};
                MMA_TF32(s[nt], qh, kh);
                MMA_TF32(s[nt], ql, kh);
                MMA_TF32(s[nt], qh, kl);
            }
        }

        const int j0 = c * 64;
        if (c >= 2 * bx) {
            #pragma unroll
            for (int nt = 0; nt < 8; nt++) {
                #pragma unroll
                for (int j = 0; j < 4; j++) {
                    int col = j0 + nt * 8 + c4l * 2 + (j & 1);
                    int row = (j < 2) ? row0 : row0 + 8;
                    s[nt][j] = (col <= row) ? s[nt][j] * 0.125f : -1e30f;
                }
            }
        } else {
            #pragma unroll
            for (int nt = 0; nt < 8; nt++)
                #pragma unroll
                for (int j = 0; j < 4; j++) s[nt][j] *= 0.125f;
        }

        float mt0 = -1e30f, mt1 = -1e30f;
        #pragma unroll
        for (int nt = 0; nt < 8; nt++) {
            mt0 = fmaxf(mt0, fmaxf(s[nt][0], s[nt][1]));
            mt1 = fmaxf(mt1, fmaxf(s[nt][2], s[nt][3]));
        }
        mt0 = fmaxf(mt0, __shfl_xor_sync(0xffffffffu, mt0, 1));
        mt0 = fmaxf(mt0, __shfl_xor_sync(0xffffffffu, mt0, 2));
        mt1 = fmaxf(mt1, __shfl_xor_sync(0xffffffffu, mt1, 1));
        mt1 = fmaxf(mt1, __shfl_xor_sync(0xffffffffu, mt1, 2));

        float m0n = fmaxf(m0, mt0), m1n = fmaxf(m1, mt1);
        float a0 = __expf(m0 - m0n), a1 = __expf(m1 - m1n);
        m0 = m0n; m1 = m1n;

        float lt0 = 0.f, lt1 = 0.f;
        #pragma unroll
        for (int nt = 0; nt < 8; nt++) {
            s[nt][0] = __expf(s[nt][0] - m0n);
            s[nt][1] = __expf(s[nt][1] - m0n);
            s[nt][2] = __expf(s[nt][2] - m1n);
            s[nt][3] = __expf(s[nt][3] - m1n);
            lt0 += s[nt][0] + s[nt][1];
            lt1 += s[nt][2] + s[nt][3];
        }
        lt0 += __shfl_xor_sync(0xffffffffu, lt0, 1);
        lt0 += __shfl_xor_sync(0xffffffffu, lt0, 2);
        lt1 += __shfl_xor_sync(0xffffffffu, lt1, 1);
        lt1 += __shfl_xor_sync(0xffffffffu, lt1, 2);
        l0 = l0 * a0 + lt0;
        l1 = l1 * a1 + lt1;

        #pragma unroll
        for (int nt = 0; nt < 8; nt++) {
            o[nt][0] *= a0; o[nt][1] *= a0;
            o[nt][2] *= a1; o[nt][3] *= a1;
        }

        #pragma unroll
        for (int ks2 = 0; ks2 < 8; ks2++) {
            float v0a = __shfl_sync(0xffffffffu, s[ks2][0], idx1);
            float v0b = __shfl_sync(0xffffffffu, s[ks2][1], idx1);
            float v2a = __shfl_sync(0xffffffffu, s[ks2][0], idx2);
            float v2b = __shfl_sync(0xffffffffu, s[ks2][1], idx2);
            float v1a = __shfl_sync(0xffffffffu, s[ks2][2], idx1);
            float v1b = __shfl_sync(0xffffffffu, s[ks2][3], idx1);
            float v3a = __shfl_sync(0xffffffffu, s[ks2][2], idx2);
            float v3b = __shfl_sync(0xffffffffu, s[ks2][3], idx2);
            bool oddc = (c4l & 1);
            float af0 = oddc ? v0b : v0a;
            float af1 = oddc ? v1b : v1a;
            float af2 = oddc ? v2b : v2a;
            float af3 = oddc ? v3b : v3a;

            uint32_t pah[4], pal[4];
            cvt_hilo(af0, pah[0], pal[0]);
            cvt_hilo(af1, pah[1], pal[1]);
            cvt_hilo(af2, pah[2], pal[2]);
            cvt_hilo(af3, pah[3], pal[3]);

            #pragma unroll
            for (int nt = 0; nt < 8; nt++) {
                uint2 vh2 = *(const uint2*)&VF[(nt * 8 + ks2) * 64 + lane * 2];
                uint2 vl2 = *(const uint2*)&VF[4096 + (nt * 8 + ks2) * 64 + lane * 2];
                uint32_t vh[2] = {vh2.x, vh2.y};
                uint32_t vl[2] = {vl2.x, vl2.y};
                MMA_TF32(o[nt], pah, vh);
                MMA_TF32(o[nt], pal, vh);
                MMA_TF32(o[nt], pah, vl);
            }
        }
        __syncthreads();
    }

    // epilogue: normalize, convert acc->A-frag (same validated shuffle), store
    float inv0 = 1.0f / l0, inv1 = 1.0f / l1;
    #pragma unroll
    for (int nt = 0; nt < 8; nt++) {
        float n0 = o[nt][0] * inv0, n1 = o[nt][1] * inv0;
        float n2 = o[nt][2] * inv1, n3 = o[nt][3] * inv1;

        float v0a = __shfl_sync(0xffffffffu, n0, idx1);
        float v0b = __shfl_sync(0xffffffffu, n1, idx1);
        float v2a = __shfl_sync(0xffffffffu, n0, idx2);
        float v2b = __shfl_sync(0xffffffffu, n1, idx2);
        float v1a = __shfl_sync(0xffffffffu, n2, idx1);
        float v1b = __shfl_sync(0xffffffffu, n3, idx1);
        float v3a = __shfl_sync(0xffffffffu, n2, idx2);
        float v3b = __shfl_sync(0xffffffffu, n3, idx2);
        bool oddc = (c4l & 1);
        float af0 = oddc ? v0b : v0a;
        float af1 = oddc ? v1b : v1a;
        float af2 = oddc ? v2b : v2a;
        float af3 = oddc ? v3b : v3a;

        uint32_t hi[4], lo[4];
        cvt_hilo(af0, hi[0], lo[0]);
        cvt_hilo(af1, hi[1], lo[1]);
        cvt_hilo(af2, hi[2], lo[2]);
        cvt_hilo(af3, hi[3], lo[3]);

        size_t base = ((size_t)(b * 16 + bx) * 32 + h * 2 + (nt >> 2)) * 8192;
        int word = ((wid * 4 + (nt & 3)) * 32 + lane) * 4;
        *(uint4*)(Ap + base + word)        = make_uint4(hi[0], hi[1], hi[2], hi[3]);
        *(uint4*)(Ap + base + 4096 + word) = make_uint4(lo[0], lo[1], lo[2], lo[3]);
    }
}

// ---------------------------------------------------------------------------
extern "C" void kernel_launch(void* const* d_in, const int* in_sizes, int n_in,
                              void* d_out, int out_size)
{
    const float* x     = (const float*)d_in[0];
    const float* w_qkv = (const float*)d_in[1];
    const float* w_out = (const float*)d_in[2];
    for (int i = 0; i < n_in; i++) {
        if      (in_sizes[i] == M_TOK * D_MODEL)       x     = (const float*)d_in[i];
        else if (in_sizes[i] == 3 * D_MODEL * D_MODEL) w_qkv = (const float*)d_in[i];
        else if (in_sizes[i] == D_MODEL * D_MODEL)     w_out = (const float*)d_in[i];
    }
    float* out = (float*)d_out;

    float *qkv = nullptr;
    uint32_t *xp = nullptr, *ap = nullptr, *vp = nullptr, *wqp = nullptr, *wop = nullptr;
    cudaGetSymbolAddress((void**)&qkv, g_qkv);
    cudaGetSymbolAddress((void**)&xp,  g_xpack);
    cudaGetSymbolAddress((void**)&ap,  g_attpack);
    cudaGetSymbolAddress((void**)&vp,  g_vpack);
    cudaGetSymbolAddress((void**)&wqp, g_wqkvp);
    cudaGetSymbolAddress((void**)&wop, g_woutp);

    static bool attr_set = false;
    if (!attr_set) {
        attr_set = true;
        cudaFuncSetAttribute(gemm_tf32_v2,
                             cudaFuncAttributeMaxDynamicSharedMemorySize, 128 * 1024);
        cudaFuncSetAttribute(attn_tc,
                             cudaFuncAttributeMaxDynamicSharedMemorySize, 192 * 1024);
        cudaFuncSetAttribute(rope_pack,
                             cudaFuncAttributeMaxDynamicSharedMemorySize, 112 * 1024);
    }

    // 0) trig table + GEMM operand packs
    trig_kernel<<<(SEQ * 32) / 256, 256>>>();
    pack_a_tf32<<<(M_TOK * 1024 / 4) / 256, 256>>>(x, xp);
    pack_b_tf32<<<(3 * D_MODEL * 1024 / 4) / 256, 256>>>(w_qkv, wqp);
    pack_b_tf32<<<(D_MODEL * 1024 / 4) / 256, 256>>>(w_out, wop);

    // 1) QKV projection -> g_qkv
    gemm_tf32_v2<<<dim3(3 * D_MODEL / 128, M_TOK / 128), 256, 128 * 1024>>>(
        xp, wqp, qkv, M_TOK, 3 * D_MODEL, D_MODEL);

    // 2) Fused rope + Q/K/V fragment pack (Qp=g_xpack, Kp=g_attpack, Vp=g_vpack)
    rope_pack<<<dim3(16, 64), 256, 112 * 1024>>>(xp, ap, vp);

    // 3) Tensor-core flash attention; epilogue emits out-proj A-frags into g_qkv
    attn_tc<<<dim3(SEQ / 128, BATCH * N_HEADS), 256, 192 * 1024>>>(
        xp, ap, vp, (uint32_t*)qkv);

    // 4) Output projection (reads A-frags from g_qkv)
    gemm_tf32_v2<<<dim3(D_MODEL / 128, M_TOK / 128), 256, 128 * 1024>>>(
        (const uint32_t*)qkv, wop, out, M_TOK, D_MODEL, D_MODEL);
}